// round 1
// baseline (speedup 1.0000x reference)
#include <cuda_runtime.h>
#include <math.h>

#define Bn 4
#define Sn 2048
#define Dn 1024
#define NH 16
#define DH 64
#define Mrows (Bn*Sn)      // 8192
#define N3 (3*Dn)          // 3072

// Scratch (device globals: allocation-free per harness rules)
__device__ float g_qkv[(size_t)Mrows * N3];   // 96 MB
__device__ float g_z[(size_t)Mrows * Dn];     // 32 MB

// ---------------------------------------------------------------------------
// Tiled GEMM: C[M,N] = A[M,K] @ W[K,N] + bias[N]
// blocktile 64x64, ktile 16, 256 threads, 4x4 microtile
// ---------------------------------------------------------------------------
__global__ void gemm_bias_kernel(const float* __restrict__ A,
                                 const float* __restrict__ W,
                                 const float* __restrict__ bias,
                                 float* __restrict__ C,
                                 int Nz, int Kz) {
    __shared__ float As[16][65];   // [kk][i]  (A transposed in smem)
    __shared__ float Bs[16][65];   // [kk][j]
    const int tid = threadIdx.x;
    const int tx = tid & 15, ty = tid >> 4;
    const int rowBase = blockIdx.y * 64;
    const int colBase = blockIdx.x * 64;

    float acc[4][4] = {};

    for (int k0 = 0; k0 < Kz; k0 += 16) {
        #pragma unroll
        for (int it = 0; it < 4; it++) {
            int idx = tid + it * 256;
            int i = idx >> 4, kk = idx & 15;
            As[kk][i] = A[(size_t)(rowBase + i) * Kz + k0 + kk];
        }
        #pragma unroll
        for (int it = 0; it < 4; it++) {
            int idx = tid + it * 256;
            int kk = idx >> 6, j = idx & 63;
            Bs[kk][j] = W[(size_t)(k0 + kk) * Nz + colBase + j];
        }
        __syncthreads();
        #pragma unroll
        for (int kk = 0; kk < 16; kk++) {
            float a[4], b[4];
            #pragma unroll
            for (int r = 0; r < 4; r++) a[r] = As[kk][ty * 4 + r];
            #pragma unroll
            for (int c = 0; c < 4; c++) b[c] = Bs[kk][tx * 4 + c];
            #pragma unroll
            for (int r = 0; r < 4; r++)
                #pragma unroll
                for (int c = 0; c < 4; c++)
                    acc[r][c] += a[r] * b[c];
        }
        __syncthreads();
    }

    #pragma unroll
    for (int r = 0; r < 4; r++) {
        int row = rowBase + ty * 4 + r;
        #pragma unroll
        for (int c = 0; c < 4; c++) {
            int col = colBase + tx * 4 + c;
            C[(size_t)row * Nz + col] = acc[r][c] + bias[col];
        }
    }
}

// ---------------------------------------------------------------------------
// RMSNorm over q and k head-rows, in place inside g_qkv.
// One warp per (row, head, which). which: 0=q (cols 0..1023), 1=k (1024..2047)
// ---------------------------------------------------------------------------
__global__ void rmsnorm_kernel(const float* __restrict__ wq,
                               const float* __restrict__ wk) {
    int gw = (blockIdx.x * blockDim.x + threadIdx.x) >> 5;
    int lane = threadIdx.x & 31;
    int which = gw & 1;
    int head = (gw >> 1) & 15;
    int row = gw >> 5;
    if (row >= Mrows) return;

    float* p = g_qkv + (size_t)row * N3 + which * Dn + head * DH;
    float2 v = ((float2*)p)[lane];
    float ss = v.x * v.x + v.y * v.y;
    #pragma unroll
    for (int o = 16; o; o >>= 1) ss += __shfl_xor_sync(0xffffffffu, ss, o);
    float inv = rsqrtf(ss * (1.0f / DH) + 1e-6f);
    const float* w = which ? wk : wq;
    float2 wv = ((const float2*)w)[lane];
    v.x *= inv * wv.x;
    v.y *= inv * wv.y;
    ((float2*)p)[lane] = v;
}

// ---------------------------------------------------------------------------
// Flash attention (causal, no 1/sqrt(d) scale — faithful to reference).
// One block = one (b, h, 64-row q tile). 256 threads, 4x4 microtile.
// Online softmax with running (m, l) per row; skips fully-masked k tiles.
// Smem: sQ[d][i], sK[d][j], sV[k][c], sP[j][i] all pitch 65 (conflict-free
// transpose stores + broadcast reads).
// ---------------------------------------------------------------------------
__global__ void attn_kernel() {
    extern __shared__ float sm[];
    float (*sQ)[65] = (float(*)[65])(sm);
    float (*sK)[65] = (float(*)[65])(sm + 64 * 65);
    float (*sV)[65] = (float(*)[65])(sm + 2 * 64 * 65);
    float (*sP)[65] = (float(*)[65])(sm + 3 * 64 * 65);

    const int tid = threadIdx.x;
    const int tx = tid & 15, ty = tid >> 4;
    const int qt = blockIdx.x;          // q tile (0..31)
    const int h  = blockIdx.y;
    const int b  = blockIdx.z;

    const size_t rowQ0 = (size_t)b * Sn + qt * 64;
    const int qoff = h * DH;            // q section
    const int koff = Dn + h * DH;       // k section
    const int voff = 2 * Dn + h * DH;   // v section

    // Load Q tile transposed: sQ[d][i]
    #pragma unroll
    for (int it = 0; it < 16; it++) {
        int idx = tid + it * 256;       // 0..4095
        int i = idx >> 6, d = idx & 63;
        sQ[d][i] = g_qkv[(rowQ0 + i) * N3 + qoff + d];
    }

    float o[4][4] = {};
    float m_prev[4], l_run[4];
    #pragma unroll
    for (int r = 0; r < 4; r++) { m_prev[r] = -INFINITY; l_run[r] = 0.0f; }

    __syncthreads();

    for (int kt = 0; kt <= qt; kt++) {
        const size_t rowK0 = (size_t)b * Sn + kt * 64;
        // Load K tile transposed sK[d][j], V tile natural sV[k][c]
        #pragma unroll
        for (int it = 0; it < 16; it++) {
            int idx = tid + it * 256;
            int j = idx >> 6, d = idx & 63;
            sK[d][j] = g_qkv[(rowK0 + j) * N3 + koff + d];
        }
        #pragma unroll
        for (int it = 0; it < 16; it++) {
            int idx = tid + it * 256;
            int k = idx >> 6, c = idx & 63;
            sV[k][c] = g_qkv[(rowK0 + k) * N3 + voff + c];
        }
        __syncthreads();

        // S = Q @ K^T  (4x4 per thread: rows ty*4+r, cols tx*4+c)
        float s[4][4] = {};
        #pragma unroll
        for (int d = 0; d < 64; d++) {
            float a[4], bb[4];
            #pragma unroll
            for (int r = 0; r < 4; r++) a[r] = sQ[d][ty * 4 + r];
            #pragma unroll
            for (int c = 0; c < 4; c++) bb[c] = sK[d][tx * 4 + c];
            #pragma unroll
            for (int r = 0; r < 4; r++)
                #pragma unroll
                for (int c = 0; c < 4; c++)
                    s[r][c] += a[r] * bb[c];
        }

        // Causal mask (only the diagonal tile has masked entries)
        if (kt == qt) {
            #pragma unroll
            for (int r = 0; r < 4; r++)
                #pragma unroll
                for (int c = 0; c < 4; c++)
                    if (tx * 4 + c > ty * 4 + r) s[r][c] = -INFINITY;
        }

        // Online softmax per row (16 lanes of same ty own one row-group)
        #pragma unroll
        for (int r = 0; r < 4; r++) {
            float rm = fmaxf(fmaxf(s[r][0], s[r][1]), fmaxf(s[r][2], s[r][3]));
            #pragma unroll
            for (int off = 8; off; off >>= 1)
                rm = fmaxf(rm, __shfl_xor_sync(0xffffffffu, rm, off));
            float m_new = fmaxf(m_prev[r], rm);
            float rs = 0.0f;
            #pragma unroll
            for (int c = 0; c < 4; c++) {
                s[r][c] = __expf(s[r][c] - m_new);   // exp(-inf)=0 handles mask
                rs += s[r][c];
            }
            #pragma unroll
            for (int off = 8; off; off >>= 1)
                rs += __shfl_xor_sync(0xffffffffu, rs, off);
            float scale = __expf(m_prev[r] - m_new);
            l_run[r] = l_run[r] * scale + rs;
            m_prev[r] = m_new;
            #pragma unroll
            for (int c = 0; c < 4; c++) o[r][c] *= scale;
        }

        // Write P transposed: sP[j][i]
        #pragma unroll
        for (int r = 0; r < 4; r++)
            #pragma unroll
            for (int c = 0; c < 4; c++)
                sP[tx * 4 + c][ty * 4 + r] = s[r][c];
        __syncthreads();

        // O += P @ V
        #pragma unroll
        for (int kk = 0; kk < 64; kk++) {
            float a[4], bb[4];
            #pragma unroll
            for (int r = 0; r < 4; r++) a[r] = sP[kk][ty * 4 + r];
            #pragma unroll
            for (int c = 0; c < 4; c++) bb[c] = sV[kk][tx * 4 + c];
            #pragma unroll
            for (int r = 0; r < 4; r++)
                #pragma unroll
                for (int c = 0; c < 4; c++)
                    o[r][c] += a[r] * bb[c];
        }
        __syncthreads();
    }

    // Finalize: z[row, h*64 + col] = o / l
    #pragma unroll
    for (int r = 0; r < 4; r++) {
        size_t row = rowQ0 + ty * 4 + r;
        float invl = 1.0f / l_run[r];
        #pragma unroll
        for (int c = 0; c < 4; c++)
            g_z[row * Dn + h * DH + tx * 4 + c] = o[r][c] * invl;
    }
}

// ---------------------------------------------------------------------------
extern "C" void kernel_launch(void* const* d_in, const int* in_sizes, int n_in,
                              void* d_out, int out_size) {
    const float* x     = (const float*)d_in[0];
    // d_in[1] = mask (unused; causal structure computed directly)
    const float* W_qkv = (const float*)d_in[2];
    const float* b_qkv = (const float*)d_in[3];
    const float* W_o   = (const float*)d_in[4];
    const float* b_o   = (const float*)d_in[5];
    const float* wq    = (const float*)d_in[6];
    const float* wk    = (const float*)d_in[7];
    float* out = (float*)d_out;

    void* qkv_ptr = nullptr;
    void* z_ptr   = nullptr;
    cudaGetSymbolAddress(&qkv_ptr, g_qkv);
    cudaGetSymbolAddress(&z_ptr, g_z);

    // 1) QKV GEMM: [8192,1024] @ [1024,3072] + b
    {
        dim3 grid(N3 / 64, Mrows / 64);
        gemm_bias_kernel<<<grid, 256>>>(x, W_qkv, b_qkv, (float*)qkv_ptr, N3, Dn);
    }

    // 2) RMSNorm on q and k (in place)
    {
        int total_warps = Mrows * NH * 2;                 // 262144
        int blocks = (total_warps * 32) / 256;            // 32768
        rmsnorm_kernel<<<blocks, 256>>>(wq, wk);
    }

    // 3) Flash attention
    {
        const int smem_bytes = 4 * 64 * 65 * (int)sizeof(float);   // 66560
        cudaFuncSetAttribute(attn_kernel,
                             cudaFuncAttributeMaxDynamicSharedMemorySize,
                             smem_bytes);
        dim3 grid(Sn / 64, NH, Bn);
        attn_kernel<<<grid, 256, smem_bytes>>>();
    }

    // 4) Output projection: [8192,1024] @ [1024,1024] + b_o
    {
        dim3 grid(Dn / 64, Mrows / 64);
        gemm_bias_kernel<<<grid, 256>>>((const float*)z_ptr, W_o, b_o, out, Dn, Dn);
    }
}

// round 3
// speedup vs baseline: 1.3618x; 1.3618x over previous
#include <cuda_runtime.h>
#include <cuda_bf16.h>
#include <math.h>

#define Bn 4
#define Sn 2048
#define Dn 1024
#define NH 16
#define DH 64
#define Mrows (Bn*Sn)      // 8192
#define N3 (3*Dn)          // 3072

// Scratch (device globals: allocation-free per harness rules)
__device__ float g_qkv[(size_t)Mrows * N3];   // 96 MB
__device__ float g_z[(size_t)Mrows * Dn];     // 32 MB

// ---------------------------------------------------------------------------
// bf16x3 split tensor-core GEMM: C = A @ W + bias  (~fp32 accuracy)
// A*B ~= Ah*Bh + Ah*Bl + Al*Bh, fragments mma.m16n8k16.bf16, fp32 accum.
// 128x128 blocktile, BK=32, 256 threads = 8 warps (2m x 4n), warp = 64x32.
// ---------------------------------------------------------------------------
#define BM 128
#define BN 128
#define BK 32
#define PITCH 20   // u32 pitch for [row][kpair] tiles; conflict-free frag loads

__device__ __forceinline__ void split_bf16(float x, __nv_bfloat16& h, __nv_bfloat16& l) {
    h = __float2bfloat16_rn(x);
    l = __float2bfloat16_rn(x - __bfloat162float(h));
}
__device__ __forceinline__ unsigned pack2(__nv_bfloat16 lo, __nv_bfloat16 hi) {
    __nv_bfloat162 p(lo, hi);   // .x = low 16 bits (k), .y = high (k+1)
    return *(unsigned*)&p;
}

__global__ void gemm_bf16x3_kernel(const float* __restrict__ A,
                                   const float* __restrict__ W,
                                   const float* __restrict__ bias,
                                   float* __restrict__ C,
                                   int Nz, int Kz) {
    __shared__ unsigned sAhi[BM][PITCH];
    __shared__ unsigned sAlo[BM][PITCH];
    __shared__ unsigned sBhi[BN][PITCH];
    __shared__ unsigned sBlo[BN][PITCH];

    const int tid  = threadIdx.x;
    const int lane = tid & 31;
    const int wid  = tid >> 5;
    const int wm   = wid >> 2;        // 0..1  -> 64-row slab
    const int wn   = wid & 3;         // 0..3  -> 32-col slab
    const int g    = lane >> 2;       // 0..7
    const int tig  = lane & 3;        // 0..3

    const int rowBase = blockIdx.y * BM;
    const int colBase = blockIdx.x * BN;

    float acc[4][4][4];
    #pragma unroll
    for (int i = 0; i < 4; i++)
        #pragma unroll
        for (int j = 0; j < 4; j++)
            #pragma unroll
            for (int q = 0; q < 4; q++) acc[i][j][q] = 0.0f;

    for (int k0 = 0; k0 < Kz; k0 += BK) {
        // --- Load + split A tile (128 x 32) ---
        #pragma unroll
        for (int it = 0; it < 4; it++) {
            int f4id = tid + it * 256;          // 0..1023
            int r  = f4id >> 3;                 // 0..127
            int c4 = f4id & 7;                  // 0..7 -> k offset 4*c4
            float4 v = *(const float4*)&A[(size_t)(rowBase + r) * Kz + k0 + c4 * 4];
            __nv_bfloat16 h0,l0,h1,l1,h2,l2,h3,l3;
            split_bf16(v.x, h0, l0); split_bf16(v.y, h1, l1);
            split_bf16(v.z, h2, l2); split_bf16(v.w, h3, l3);
            sAhi[r][c4 * 2]     = pack2(h0, h1);
            sAhi[r][c4 * 2 + 1] = pack2(h2, h3);
            sAlo[r][c4 * 2]     = pack2(l0, l1);
            sAlo[r][c4 * 2 + 1] = pack2(l2, l3);
        }
        // --- Load + split W tile (32 x 128), store as [n][kpair] ---
        #pragma unroll
        for (int it = 0; it < 2; it++) {
            int id = tid + it * 256;            // 0..511
            int kp = id >> 5;                   // 0..15
            int n4 = id & 31;                   // 0..31
            const float* wp = &W[(size_t)(k0 + 2 * kp) * Nz + colBase + n4 * 4];
            float4 v0 = *(const float4*)wp;
            float4 v1 = *(const float4*)(wp + Nz);
            float e0[4] = {v0.x, v0.y, v0.z, v0.w};
            float e1[4] = {v1.x, v1.y, v1.z, v1.w};
            #pragma unroll
            for (int j = 0; j < 4; j++) {
                __nv_bfloat16 ha,la,hb,lb;
                split_bf16(e0[j], ha, la);
                split_bf16(e1[j], hb, lb);
                sBhi[n4 * 4 + j][kp] = pack2(ha, hb);
                sBlo[n4 * 4 + j][kp] = pack2(la, lb);
            }
        }
        __syncthreads();

        #pragma unroll
        for (int kk = 0; kk < BK; kk += 16) {
            const int pa = (kk >> 1) + tig;     // kpair index
            unsigned ahi[4][4], alo[4][4], bhi[4][2], blo[4][2];
            #pragma unroll
            for (int mi = 0; mi < 4; mi++) {
                int m0 = wm * 64 + mi * 16;
                ahi[mi][0] = sAhi[m0 + g][pa];
                ahi[mi][1] = sAhi[m0 + g + 8][pa];
                ahi[mi][2] = sAhi[m0 + g][pa + 4];
                ahi[mi][3] = sAhi[m0 + g + 8][pa + 4];
                alo[mi][0] = sAlo[m0 + g][pa];
                alo[mi][1] = sAlo[m0 + g + 8][pa];
                alo[mi][2] = sAlo[m0 + g][pa + 4];
                alo[mi][3] = sAlo[m0 + g + 8][pa + 4];
            }
            #pragma unroll
            for (int ni = 0; ni < 4; ni++) {
                int n0 = wn * 32 + ni * 8;
                bhi[ni][0] = sBhi[n0 + g][pa];
                bhi[ni][1] = sBhi[n0 + g][pa + 4];
                blo[ni][0] = sBlo[n0 + g][pa];
                blo[ni][1] = sBlo[n0 + g][pa + 4];
            }
            #pragma unroll
            for (int mi = 0; mi < 4; mi++)
                #pragma unroll
                for (int ni = 0; ni < 4; ni++) {
                    #define MMA(AF, BF)                                            \
                        asm volatile(                                              \
                            "mma.sync.aligned.m16n8k16.row.col.f32.bf16.bf16.f32 " \
                            "{%0,%1,%2,%3}, {%4,%5,%6,%7}, {%8,%9}, {%0,%1,%2,%3};"\
                            : "+f"(acc[mi][ni][0]), "+f"(acc[mi][ni][1]),          \
                              "+f"(acc[mi][ni][2]), "+f"(acc[mi][ni][3])           \
                            : "r"(AF[mi][0]), "r"(AF[mi][1]),                      \
                              "r"(AF[mi][2]), "r"(AF[mi][3]),                      \
                              "r"(BF[ni][0]), "r"(BF[ni][1]))
                    MMA(ahi, bhi);
                    MMA(ahi, blo);
                    MMA(alo, bhi);
                    #undef MMA
                }
        }
        __syncthreads();
    }

    // Epilogue: add bias, write (c0=(g,2t), c1=(g,2t+1), c2/c3 = +8 rows)
    #pragma unroll
    for (int mi = 0; mi < 4; mi++) {
        int row0 = rowBase + wm * 64 + mi * 16 + g;
        int row1 = row0 + 8;
        #pragma unroll
        for (int ni = 0; ni < 4; ni++) {
            int col = colBase + wn * 32 + ni * 8 + tig * 2;
            float b0 = __ldg(&bias[col]);
            float b1 = __ldg(&bias[col + 1]);
            C[(size_t)row0 * Nz + col]     = acc[mi][ni][0] + b0;
            C[(size_t)row0 * Nz + col + 1] = acc[mi][ni][1] + b1;
            C[(size_t)row1 * Nz + col]     = acc[mi][ni][2] + b0;
            C[(size_t)row1 * Nz + col + 1] = acc[mi][ni][3] + b1;
        }
    }
}

// ---------------------------------------------------------------------------
// RMSNorm over q and k head-rows, in place inside g_qkv.
// ---------------------------------------------------------------------------
__global__ void rmsnorm_kernel(const float* __restrict__ wq,
                               const float* __restrict__ wk) {
    int gw = (blockIdx.x * blockDim.x + threadIdx.x) >> 5;
    int lane = threadIdx.x & 31;
    int which = gw & 1;
    int head = (gw >> 1) & 15;
    int row = gw >> 5;
    if (row >= Mrows) return;

    float* p = g_qkv + (size_t)row * N3 + which * Dn + head * DH;
    float2 v = ((float2*)p)[lane];
    float ss = v.x * v.x + v.y * v.y;
    #pragma unroll
    for (int o = 16; o; o >>= 1) ss += __shfl_xor_sync(0xffffffffu, ss, o);
    float inv = rsqrtf(ss * (1.0f / DH) + 1e-6f);
    const float* w = which ? wk : wq;
    float2 wv = ((const float2*)w)[lane];
    v.x *= inv * wv.x;
    v.y *= inv * wv.y;
    ((float2*)p)[lane] = v;
}

// ---------------------------------------------------------------------------
// Flash attention (causal, no 1/sqrt(d) scale — faithful to reference).
// One block = one (b, h, 64-row q tile). 256 threads, 4x4 microtile.
// ---------------------------------------------------------------------------
__global__ void attn_kernel() {
    extern __shared__ float sm[];
    float (*sQ)[65] = (float(*)[65])(sm);
    float (*sK)[65] = (float(*)[65])(sm + 64 * 65);
    float (*sV)[65] = (float(*)[65])(sm + 2 * 64 * 65);
    float (*sP)[65] = (float(*)[65])(sm + 3 * 64 * 65);

    const int tid = threadIdx.x;
    const int tx = tid & 15, ty = tid >> 4;
    const int qt = blockIdx.x;
    const int h  = blockIdx.y;
    const int b  = blockIdx.z;

    const size_t rowQ0 = (size_t)b * Sn + qt * 64;
    const int qoff = h * DH;
    const int koff = Dn + h * DH;
    const int voff = 2 * Dn + h * DH;

    #pragma unroll
    for (int it = 0; it < 16; it++) {
        int idx = tid + it * 256;
        int i = idx >> 6, d = idx & 63;
        sQ[d][i] = g_qkv[(rowQ0 + i) * N3 + qoff + d];
    }

    float o[4][4] = {};
    float m_prev[4], l_run[4];
    #pragma unroll
    for (int r = 0; r < 4; r++) { m_prev[r] = -INFINITY; l_run[r] = 0.0f; }

    __syncthreads();

    for (int kt = 0; kt <= qt; kt++) {
        const size_t rowK0 = (size_t)b * Sn + kt * 64;
        #pragma unroll
        for (int it = 0; it < 16; it++) {
            int idx = tid + it * 256;
            int j = idx >> 6, d = idx & 63;
            sK[d][j] = g_qkv[(rowK0 + j) * N3 + koff + d];
        }
        #pragma unroll
        for (int it = 0; it < 16; it++) {
            int idx = tid + it * 256;
            int k = idx >> 6, c = idx & 63;
            sV[k][c] = g_qkv[(rowK0 + k) * N3 + voff + c];
        }
        __syncthreads();

        float s[4][4] = {};
        #pragma unroll
        for (int d = 0; d < 64; d++) {
            float a[4], bb[4];
            #pragma unroll
            for (int r = 0; r < 4; r++) a[r] = sQ[d][ty * 4 + r];
            #pragma unroll
            for (int c = 0; c < 4; c++) bb[c] = sK[d][tx * 4 + c];
            #pragma unroll
            for (int r = 0; r < 4; r++)
                #pragma unroll
                for (int c = 0; c < 4; c++)
                    s[r][c] += a[r] * bb[c];
        }

        if (kt == qt) {
            #pragma unroll
            for (int r = 0; r < 4; r++)
                #pragma unroll
                for (int c = 0; c < 4; c++)
                    if (tx * 4 + c > ty * 4 + r) s[r][c] = -INFINITY;
        }

        #pragma unroll
        for (int r = 0; r < 4; r++) {
            float rm = fmaxf(fmaxf(s[r][0], s[r][1]), fmaxf(s[r][2], s[r][3]));
            #pragma unroll
            for (int off = 8; off; off >>= 1)
                rm = fmaxf(rm, __shfl_xor_sync(0xffffffffu, rm, off));
            float m_new = fmaxf(m_prev[r], rm);
            float rs = 0.0f;
            #pragma unroll
            for (int c = 0; c < 4; c++) {
                s[r][c] = __expf(s[r][c] - m_new);
                rs += s[r][c];
            }
            #pragma unroll
            for (int off = 8; off; off >>= 1)
                rs += __shfl_xor_sync(0xffffffffu, rs, off);
            float scale = __expf(m_prev[r] - m_new);
            l_run[r] = l_run[r] * scale + rs;
            m_prev[r] = m_new;
            #pragma unroll
            for (int c = 0; c < 4; c++) o[r][c] *= scale;
        }

        #pragma unroll
        for (int r = 0; r < 4; r++)
            #pragma unroll
            for (int c = 0; c < 4; c++)
                sP[tx * 4 + c][ty * 4 + r] = s[r][c];
        __syncthreads();

        #pragma unroll
        for (int kk = 0; kk < 64; kk++) {
            float a[4], bb[4];
            #pragma unroll
            for (int r = 0; r < 4; r++) a[r] = sP[kk][ty * 4 + r];
            #pragma unroll
            for (int c = 0; c < 4; c++) bb[c] = sV[kk][tx * 4 + c];
            #pragma unroll
            for (int r = 0; r < 4; r++)
                #pragma unroll
                for (int c = 0; c < 4; c++)
                    o[r][c] += a[r] * bb[c];
        }
        __syncthreads();
    }

    #pragma unroll
    for (int r = 0; r < 4; r++) {
        size_t row = rowQ0 + ty * 4 + r;
        float invl = 1.0f / l_run[r];
        #pragma unroll
        for (int c = 0; c < 4; c++)
            g_z[row * Dn + h * DH + tx * 4 + c] = o[r][c] * invl;
    }
}

// ---------------------------------------------------------------------------
extern "C" void kernel_launch(void* const* d_in, const int* in_sizes, int n_in,
                              void* d_out, int out_size) {
    const float* x     = (const float*)d_in[0];
    const float* W_qkv = (const float*)d_in[2];
    const float* b_qkv = (const float*)d_in[3];
    const float* W_o   = (const float*)d_in[4];
    const float* b_o   = (const float*)d_in[5];
    const float* wq    = (const float*)d_in[6];
    const float* wk    = (const float*)d_in[7];
    float* out = (float*)d_out;

    void* qkv_ptr = nullptr;
    void* z_ptr   = nullptr;
    cudaGetSymbolAddress(&qkv_ptr, g_qkv);
    cudaGetSymbolAddress(&z_ptr, g_z);

    // 1) QKV GEMM (bf16x3 tensor cores)
    {
        dim3 grid(N3 / BN, Mrows / BM);
        gemm_bf16x3_kernel<<<grid, 256>>>(x, W_qkv, b_qkv, (float*)qkv_ptr, N3, Dn);
    }

    // 2) RMSNorm on q and k (in place)
    {
        int total_warps = Mrows * NH * 2;
        int blocks = (total_warps * 32) / 256;
        rmsnorm_kernel<<<blocks, 256>>>(wq, wk);
    }

    // 3) Flash attention
    {
        const int smem_bytes = 4 * 64 * 65 * (int)sizeof(float);
        cudaFuncSetAttribute(attn_kernel,
                             cudaFuncAttributeMaxDynamicSharedMemorySize,
                             smem_bytes);
        dim3 grid(Sn / 64, NH, Bn);
        attn_kernel<<<grid, 256, smem_bytes>>>();
    }

    // 4) Output projection (bf16x3 tensor cores)
    {
        dim3 grid(Dn / BN, Mrows / BM);
        gemm_bf16x3_kernel<<<grid, 256>>>((const float*)z_ptr, W_o, b_o, out, Dn, Dn);
    }
}

// round 4
// speedup vs baseline: 1.8266x; 1.3413x over previous
#include <cuda_runtime.h>
#include <cuda_bf16.h>
#include <math.h>

#define Bn 4
#define Sn 2048
#define Dn 1024
#define NH 16
#define DH 64
#define Mrows (Bn*Sn)      // 8192
#define N3 (3*Dn)          // 3072

// Scratch (device globals: allocation-free per harness rules)
__device__ float g_qkv[(size_t)Mrows * N3];            // 96 MB
__device__ float g_z[(size_t)Mrows * Dn];              // 32 MB
__device__ __nv_bfloat16 g_Ah[(size_t)Mrows * Dn];     // 16 MB (x split, reused for z)
__device__ __nv_bfloat16 g_Al[(size_t)Mrows * Dn];     // 16 MB
__device__ __nv_bfloat16 g_Wth[(size_t)N3 * Dn];       // W_qkv^T hi  [N][K]
__device__ __nv_bfloat16 g_Wtl[(size_t)N3 * Dn];
__device__ __nv_bfloat16 g_Woth[(size_t)Dn * Dn];      // W_o^T hi
__device__ __nv_bfloat16 g_Wotl[(size_t)Dn * Dn];

__device__ __forceinline__ void split_bf16(float x, __nv_bfloat16& h, __nv_bfloat16& l) {
    h = __float2bfloat16_rn(x);
    l = __float2bfloat16_rn(x - __bfloat162float(h));
}

// ---------------------------------------------------------------------------
// Elementwise split: fp32 -> (hi, lo) bf16
// ---------------------------------------------------------------------------
__global__ void split_kernel(const float* __restrict__ in,
                             __nv_bfloat16* __restrict__ h,
                             __nv_bfloat16* __restrict__ l, size_t n4) {
    size_t i = (size_t)blockIdx.x * blockDim.x + threadIdx.x;
    size_t stride = (size_t)gridDim.x * blockDim.x;
    for (; i < n4; i += stride) {
        float4 v = ((const float4*)in)[i];
        __nv_bfloat16 h0,l0,h1,l1,h2,l2,h3,l3;
        split_bf16(v.x, h0, l0); split_bf16(v.y, h1, l1);
        split_bf16(v.z, h2, l2); split_bf16(v.w, h3, l3);
        __nv_bfloat162 hh0(h0, h1), hh1(h2, h3), ll0(l0, l1), ll1(l2, l3);
        ((__nv_bfloat162*)h)[i * 2]     = hh0;
        ((__nv_bfloat162*)h)[i * 2 + 1] = hh1;
        ((__nv_bfloat162*)l)[i * 2]     = ll0;
        ((__nv_bfloat162*)l)[i * 2 + 1] = ll1;
    }
}

// ---------------------------------------------------------------------------
// Transpose + split: W[K][N] fp32 -> Wt hi/lo [N][K] bf16
// ---------------------------------------------------------------------------
__global__ void tsplit_kernel(const float* __restrict__ W,
                              __nv_bfloat16* __restrict__ th,
                              __nv_bfloat16* __restrict__ tl, int K, int N) {
    __shared__ float t[32][33];
    int n0 = blockIdx.x * 32, k0 = blockIdx.y * 32;
    int tx = threadIdx.x, ty = threadIdx.y;           // (32, 8)
    #pragma unroll
    for (int i = ty; i < 32; i += 8)
        t[i][tx] = W[(size_t)(k0 + i) * N + n0 + tx];
    __syncthreads();
    #pragma unroll
    for (int i = ty; i < 32; i += 8) {
        float v = t[tx][i];                            // = W[k0+tx][n0+i]
        __nv_bfloat16 h, l;
        split_bf16(v, h, l);
        th[(size_t)(n0 + i) * K + k0 + tx] = h;
        tl[(size_t)(n0 + i) * K + k0 + tx] = l;
    }
}

// ---------------------------------------------------------------------------
// bf16x3 double-buffered cp.async GEMM.
// A: hi/lo bf16 [M][K]; Bt: hi/lo bf16 [N][K]; C = A@B + bias (fp32 out).
// 128x128 blocktile, BKK=64, 256 threads = 8 warps (2m x 4n).
// smem tiles as packed u32 kpairs, pitch 36 (conflict-free fragment LDS).
// ---------------------------------------------------------------------------
#define BKK 64
#define PITCH 36                       // u32 per row (32 data + 4 pad)
#define TILE_U32 (128 * PITCH)         // one matrix tile
#define STAGE_U32 (4 * TILE_U32)       // Ah, Al, Bh, Bl

__device__ __forceinline__ void cp16(unsigned smem_addr, const void* gptr) {
    asm volatile("cp.async.cg.shared.global [%0], [%1], 16;"
                 :: "r"(smem_addr), "l"(gptr));
}

__global__ __launch_bounds__(256)
void gemm_bf16x3_db(const __nv_bfloat16* __restrict__ Ah,
                    const __nv_bfloat16* __restrict__ Al,
                    const __nv_bfloat16* __restrict__ Bth,
                    const __nv_bfloat16* __restrict__ Btl,
                    const float* __restrict__ bias,
                    float* __restrict__ C, int Nz, int Kz) {
    extern __shared__ unsigned sm[];

    const int tid  = threadIdx.x;
    const int lane = tid & 31;
    const int wid  = tid >> 5;
    const int wm   = wid >> 2;
    const int wn   = wid & 3;
    const int g    = lane >> 2;
    const int tig  = lane & 3;

    const int rowBase = blockIdx.y * 128;
    const int colBase = blockIdx.x * 128;

    // per-thread cp.async mapping: 4 sectors per matrix, sector = 16B = 8 bf16
    const int r0 = tid >> 3;           // row for it4=0 (0..31), +32 per it4
    const int c8 = tid & 7;            // k-sector within row

    const unsigned smem_base = (unsigned)__cvta_generic_to_shared(sm);

    float acc[4][4][4];
    #pragma unroll
    for (int i = 0; i < 4; i++)
        #pragma unroll
        for (int j = 0; j < 4; j++)
            #pragma unroll
            for (int q = 0; q < 4; q++) acc[i][j][q] = 0.0f;

    const int NIT = Kz / BKK;

    auto load_stage = [&](int it, int buf) {
        const int k0 = it * BKK;
        const unsigned sbase = smem_base + buf * STAGE_U32 * 4;
        #pragma unroll
        for (int it4 = 0; it4 < 4; it4++) {
            int row = r0 + it4 * 32;
            unsigned soff = (unsigned)(row * PITCH + c8 * 4) * 4;
            const __nv_bfloat16* gA = Ah + (size_t)(rowBase + row) * Kz + k0 + c8 * 8;
            const __nv_bfloat16* gAl2 = Al + (size_t)(rowBase + row) * Kz + k0 + c8 * 8;
            const __nv_bfloat16* gB = Bth + (size_t)(colBase + row) * Kz + k0 + c8 * 8;
            const __nv_bfloat16* gBl2 = Btl + (size_t)(colBase + row) * Kz + k0 + c8 * 8;
            cp16(sbase + soff, gA);
            cp16(sbase + TILE_U32 * 4 + soff, gAl2);
            cp16(sbase + 2 * TILE_U32 * 4 + soff, gB);
            cp16(sbase + 3 * TILE_U32 * 4 + soff, gBl2);
        }
        asm volatile("cp.async.commit_group;");
    };

    load_stage(0, 0);

    for (int it = 0; it < NIT; it++) {
        const int buf = it & 1;
        if (it + 1 < NIT) {
            load_stage(it + 1, (it + 1) & 1);
            asm volatile("cp.async.wait_group 1;");
        } else {
            asm volatile("cp.async.wait_group 0;");
        }
        __syncthreads();

        const unsigned* sAh = sm + buf * STAGE_U32;
        const unsigned* sAl = sAh + TILE_U32;
        const unsigned* sBh = sAh + 2 * TILE_U32;
        const unsigned* sBl = sAh + 3 * TILE_U32;

        #pragma unroll
        for (int kk8 = 0; kk8 < 4; kk8++) {
            const int pa = kk8 * 8 + tig;
            unsigned ahi[4][4], alo[4][4], bhi[4][2], blo[4][2];
            #pragma unroll
            for (int mi = 0; mi < 4; mi++) {
                int m0 = wm * 64 + mi * 16;
                ahi[mi][0] = sAh[(m0 + g) * PITCH + pa];
                ahi[mi][1] = sAh[(m0 + g + 8) * PITCH + pa];
                ahi[mi][2] = sAh[(m0 + g) * PITCH + pa + 4];
                ahi[mi][3] = sAh[(m0 + g + 8) * PITCH + pa + 4];
                alo[mi][0] = sAl[(m0 + g) * PITCH + pa];
                alo[mi][1] = sAl[(m0 + g + 8) * PITCH + pa];
                alo[mi][2] = sAl[(m0 + g) * PITCH + pa + 4];
                alo[mi][3] = sAl[(m0 + g + 8) * PITCH + pa + 4];
            }
            #pragma unroll
            for (int ni = 0; ni < 4; ni++) {
                int n0 = wn * 32 + ni * 8;
                bhi[ni][0] = sBh[(n0 + g) * PITCH + pa];
                bhi[ni][1] = sBh[(n0 + g) * PITCH + pa + 4];
                blo[ni][0] = sBl[(n0 + g) * PITCH + pa];
                blo[ni][1] = sBl[(n0 + g) * PITCH + pa + 4];
            }
            #pragma unroll
            for (int mi = 0; mi < 4; mi++)
                #pragma unroll
                for (int ni = 0; ni < 4; ni++) {
                    #define MMA(AF, BF)                                            \
                        asm volatile(                                              \
                            "mma.sync.aligned.m16n8k16.row.col.f32.bf16.bf16.f32 " \
                            "{%0,%1,%2,%3}, {%4,%5,%6,%7}, {%8,%9}, {%0,%1,%2,%3};"\
                            : "+f"(acc[mi][ni][0]), "+f"(acc[mi][ni][1]),          \
                              "+f"(acc[mi][ni][2]), "+f"(acc[mi][ni][3])           \
                            : "r"(AF[mi][0]), "r"(AF[mi][1]),                      \
                              "r"(AF[mi][2]), "r"(AF[mi][3]),                      \
                              "r"(BF[ni][0]), "r"(BF[ni][1]))
                    MMA(ahi, bhi);
                    MMA(ahi, blo);
                    MMA(alo, bhi);
                    #undef MMA
                }
        }
        __syncthreads();
    }

    // Epilogue: add bias, write
    #pragma unroll
    for (int mi = 0; mi < 4; mi++) {
        int row0 = rowBase + wm * 64 + mi * 16 + g;
        int row1 = row0 + 8;
        #pragma unroll
        for (int ni = 0; ni < 4; ni++) {
            int col = colBase + wn * 32 + ni * 8 + tig * 2;
            float b0 = __ldg(&bias[col]);
            float b1 = __ldg(&bias[col + 1]);
            C[(size_t)row0 * Nz + col]     = acc[mi][ni][0] + b0;
            C[(size_t)row0 * Nz + col + 1] = acc[mi][ni][1] + b1;
            C[(size_t)row1 * Nz + col]     = acc[mi][ni][2] + b0;
            C[(size_t)row1 * Nz + col + 1] = acc[mi][ni][3] + b1;
        }
    }
}

// ---------------------------------------------------------------------------
// RMSNorm over q and k head-rows, in place inside g_qkv.
// ---------------------------------------------------------------------------
__global__ void rmsnorm_kernel(const float* __restrict__ wq,
                               const float* __restrict__ wk) {
    int gw = (blockIdx.x * blockDim.x + threadIdx.x) >> 5;
    int lane = threadIdx.x & 31;
    int which = gw & 1;
    int head = (gw >> 1) & 15;
    int row = gw >> 5;
    if (row >= Mrows) return;

    float* p = g_qkv + (size_t)row * N3 + which * Dn + head * DH;
    float2 v = ((float2*)p)[lane];
    float ss = v.x * v.x + v.y * v.y;
    #pragma unroll
    for (int o = 16; o; o >>= 1) ss += __shfl_xor_sync(0xffffffffu, ss, o);
    float inv = rsqrtf(ss * (1.0f / DH) + 1e-6f);
    const float* w = which ? wk : wq;
    float2 wv = ((const float2*)w)[lane];
    v.x *= inv * wv.x;
    v.y *= inv * wv.y;
    ((float2*)p)[lane] = v;
}

// ---------------------------------------------------------------------------
// Flash attention (causal). One block = one (b, h, 64-row q tile).
// 256 threads, 4x4 microtile. Unchanged from round 3 (known good).
// ---------------------------------------------------------------------------
__global__ void attn_kernel() {
    extern __shared__ float smf[];
    float (*sQ)[65] = (float(*)[65])(smf);
    float (*sK)[65] = (float(*)[65])(smf + 64 * 65);
    float (*sV)[65] = (float(*)[65])(smf + 2 * 64 * 65);
    float (*sP)[65] = (float(*)[65])(smf + 3 * 64 * 65);

    const int tid = threadIdx.x;
    const int tx = tid & 15, ty = tid >> 4;
    const int qt = blockIdx.x;
    const int h  = blockIdx.y;
    const int b  = blockIdx.z;

    const size_t rowQ0 = (size_t)b * Sn + qt * 64;
    const int qoff = h * DH;
    const int koff = Dn + h * DH;
    const int voff = 2 * Dn + h * DH;

    #pragma unroll
    for (int it = 0; it < 16; it++) {
        int idx = tid + it * 256;
        int i = idx >> 6, d = idx & 63;
        sQ[d][i] = g_qkv[(rowQ0 + i) * N3 + qoff + d];
    }

    float o[4][4] = {};
    float m_prev[4], l_run[4];
    #pragma unroll
    for (int r = 0; r < 4; r++) { m_prev[r] = -INFINITY; l_run[r] = 0.0f; }

    __syncthreads();

    for (int kt = 0; kt <= qt; kt++) {
        const size_t rowK0 = (size_t)b * Sn + kt * 64;
        #pragma unroll
        for (int it = 0; it < 16; it++) {
            int idx = tid + it * 256;
            int j = idx >> 6, d = idx & 63;
            sK[d][j] = g_qkv[(rowK0 + j) * N3 + koff + d];
        }
        #pragma unroll
        for (int it = 0; it < 16; it++) {
            int idx = tid + it * 256;
            int k = idx >> 6, c = idx & 63;
            sV[k][c] = g_qkv[(rowK0 + k) * N3 + voff + c];
        }
        __syncthreads();

        float s[4][4] = {};
        #pragma unroll
        for (int d = 0; d < 64; d++) {
            float a[4], bb[4];
            #pragma unroll
            for (int r = 0; r < 4; r++) a[r] = sQ[d][ty * 4 + r];
            #pragma unroll
            for (int c = 0; c < 4; c++) bb[c] = sK[d][tx * 4 + c];
            #pragma unroll
            for (int r = 0; r < 4; r++)
                #pragma unroll
                for (int c = 0; c < 4; c++)
                    s[r][c] += a[r] * bb[c];
        }

        if (kt == qt) {
            #pragma unroll
            for (int r = 0; r < 4; r++)
                #pragma unroll
                for (int c = 0; c < 4; c++)
                    if (tx * 4 + c > ty * 4 + r) s[r][c] = -INFINITY;
        }

        #pragma unroll
        for (int r = 0; r < 4; r++) {
            float rm = fmaxf(fmaxf(s[r][0], s[r][1]), fmaxf(s[r][2], s[r][3]));
            #pragma unroll
            for (int off = 8; off; off >>= 1)
                rm = fmaxf(rm, __shfl_xor_sync(0xffffffffu, rm, off));
            float m_new = fmaxf(m_prev[r], rm);
            float rs = 0.0f;
            #pragma unroll
            for (int c = 0; c < 4; c++) {
                s[r][c] = __expf(s[r][c] - m_new);
                rs += s[r][c];
            }
            #pragma unroll
            for (int off = 8; off; off >>= 1)
                rs += __shfl_xor_sync(0xffffffffu, rs, off);
            float scale = __expf(m_prev[r] - m_new);
            l_run[r] = l_run[r] * scale + rs;
            m_prev[r] = m_new;
            #pragma unroll
            for (int c = 0; c < 4; c++) o[r][c] *= scale;
        }

        #pragma unroll
        for (int r = 0; r < 4; r++)
            #pragma unroll
            for (int c = 0; c < 4; c++)
                sP[tx * 4 + c][ty * 4 + r] = s[r][c];
        __syncthreads();

        #pragma unroll
        for (int kk = 0; kk < 64; kk++) {
            float a[4], bb[4];
            #pragma unroll
            for (int r = 0; r < 4; r++) a[r] = sP[kk][ty * 4 + r];
            #pragma unroll
            for (int c = 0; c < 4; c++) bb[c] = sV[kk][tx * 4 + c];
            #pragma unroll
            for (int r = 0; r < 4; r++)
                #pragma unroll
                for (int c = 0; c < 4; c++)
                    o[r][c] += a[r] * bb[c];
        }
        __syncthreads();
    }

    #pragma unroll
    for (int r = 0; r < 4; r++) {
        size_t row = rowQ0 + ty * 4 + r;
        float invl = 1.0f / l_run[r];
        #pragma unroll
        for (int c = 0; c < 4; c++)
            g_z[row * Dn + h * DH + tx * 4 + c] = o[r][c] * invl;
    }
}

// ---------------------------------------------------------------------------
extern "C" void kernel_launch(void* const* d_in, const int* in_sizes, int n_in,
                              void* d_out, int out_size) {
    const float* x     = (const float*)d_in[0];
    const float* W_qkv = (const float*)d_in[2];
    const float* b_qkv = (const float*)d_in[3];
    const float* W_o   = (const float*)d_in[4];
    const float* b_o   = (const float*)d_in[5];
    const float* wq    = (const float*)d_in[6];
    const float* wk    = (const float*)d_in[7];
    float* out = (float*)d_out;

    void *qkv_ptr, *z_ptr, *ah, *al, *wth, *wtl, *woth, *wotl;
    cudaGetSymbolAddress(&qkv_ptr, g_qkv);
    cudaGetSymbolAddress(&z_ptr, g_z);
    cudaGetSymbolAddress(&ah, g_Ah);
    cudaGetSymbolAddress(&al, g_Al);
    cudaGetSymbolAddress(&wth, g_Wth);
    cudaGetSymbolAddress(&wtl, g_Wtl);
    cudaGetSymbolAddress(&woth, g_Woth);
    cudaGetSymbolAddress(&wotl, g_Wotl);

    const int gemm_smem = 2 * STAGE_U32 * 4;   // 147456 B
    cudaFuncSetAttribute(gemm_bf16x3_db,
                         cudaFuncAttributeMaxDynamicSharedMemorySize, gemm_smem);

    // 0) Preprocessing: split x; transpose+split weights
    split_kernel<<<1024, 256>>>(x, (__nv_bfloat16*)ah, (__nv_bfloat16*)al,
                                (size_t)Mrows * Dn / 4);
    {
        dim3 grid(N3 / 32, Dn / 32);
        tsplit_kernel<<<grid, dim3(32, 8)>>>(W_qkv, (__nv_bfloat16*)wth,
                                             (__nv_bfloat16*)wtl, Dn, N3);
    }
    {
        dim3 grid(Dn / 32, Dn / 32);
        tsplit_kernel<<<grid, dim3(32, 8)>>>(W_o, (__nv_bfloat16*)woth,
                                             (__nv_bfloat16*)wotl, Dn, Dn);
    }

    // 1) QKV GEMM
    {
        dim3 grid(N3 / 128, Mrows / 128);
        gemm_bf16x3_db<<<grid, 256, gemm_smem>>>(
            (const __nv_bfloat16*)ah, (const __nv_bfloat16*)al,
            (const __nv_bfloat16*)wth, (const __nv_bfloat16*)wtl,
            b_qkv, (float*)qkv_ptr, N3, Dn);
    }

    // 2) RMSNorm on q and k (in place)
    {
        int total_warps = Mrows * NH * 2;
        int blocks = (total_warps * 32) / 256;
        rmsnorm_kernel<<<blocks, 256>>>(wq, wk);
    }

    // 3) Flash attention
    {
        const int smem_bytes = 4 * 64 * 65 * (int)sizeof(float);
        cudaFuncSetAttribute(attn_kernel,
                             cudaFuncAttributeMaxDynamicSharedMemorySize,
                             smem_bytes);
        dim3 grid(Sn / 64, NH, Bn);
        attn_kernel<<<grid, 256, smem_bytes>>>();
    }

    // 4) Split z, then output projection
    split_kernel<<<1024, 256>>>((const float*)z_ptr, (__nv_bfloat16*)ah,
                                (__nv_bfloat16*)al, (size_t)Mrows * Dn / 4);
    {
        dim3 grid(Dn / 128, Mrows / 128);
        gemm_bf16x3_db<<<grid, 256, gemm_smem>>>(
            (const __nv_bfloat16*)ah, (const __nv_bfloat16*)al,
            (const __nv_bfloat16*)woth, (const __nv_bfloat16*)wotl,
            b_o, out, Dn, Dn);
    }
}

// round 5
// speedup vs baseline: 2.1801x; 1.1935x over previous
#include <cuda_runtime.h>
#include <cuda_bf16.h>
#include <math.h>

#define Bn 4
#define Sn 2048
#define Dn 1024
#define NH 16
#define DH 64
#define Mrows (Bn*Sn)      // 8192
#define N3 (3*Dn)          // 3072

// Scratch (device globals: allocation-free per harness rules)
__device__ float g_qkv[(size_t)Mrows * N3];            // 96 MB
__device__ float g_z[(size_t)Mrows * Dn];              // 32 MB
__device__ __nv_bfloat16 g_Ah[(size_t)Mrows * Dn];     // x / z split hi
__device__ __nv_bfloat16 g_Al[(size_t)Mrows * Dn];
__device__ __nv_bfloat16 g_Wth[(size_t)N3 * Dn];       // W_qkv^T hi [N][K]
__device__ __nv_bfloat16 g_Wtl[(size_t)N3 * Dn];
__device__ __nv_bfloat16 g_Woth[(size_t)Dn * Dn];      // W_o^T hi
__device__ __nv_bfloat16 g_Wotl[(size_t)Dn * Dn];
__device__ __nv_bfloat16 g_Qh[(size_t)Mrows * Dn];     // rmsnormed q split
__device__ __nv_bfloat16 g_Ql[(size_t)Mrows * Dn];
__device__ __nv_bfloat16 g_Kh[(size_t)Mrows * Dn];     // rmsnormed k split
__device__ __nv_bfloat16 g_Kl[(size_t)Mrows * Dn];
__device__ __nv_bfloat16 g_Vth[(size_t)Mrows * Dn];    // V^T split: [(b*NH+h)*DH+d][s]
__device__ __nv_bfloat16 g_Vtl[(size_t)Mrows * Dn];

__device__ __forceinline__ void split_bf16(float x, __nv_bfloat16& h, __nv_bfloat16& l) {
    h = __float2bfloat16_rn(x);
    l = __float2bfloat16_rn(x - __bfloat162float(h));
}
__device__ __forceinline__ unsigned pack2(__nv_bfloat16 lo, __nv_bfloat16 hi) {
    __nv_bfloat162 p(lo, hi);
    return *(unsigned*)&p;
}
__device__ __forceinline__ void mma16816(float* c, const unsigned* a, const unsigned* b) {
    asm volatile(
        "mma.sync.aligned.m16n8k16.row.col.f32.bf16.bf16.f32 "
        "{%0,%1,%2,%3}, {%4,%5,%6,%7}, {%8,%9}, {%0,%1,%2,%3};"
        : "+f"(c[0]), "+f"(c[1]), "+f"(c[2]), "+f"(c[3])
        : "r"(a[0]), "r"(a[1]), "r"(a[2]), "r"(a[3]), "r"(b[0]), "r"(b[1]));
}

// ---------------------------------------------------------------------------
// Elementwise split: fp32 -> (hi, lo) bf16
// ---------------------------------------------------------------------------
__global__ void split_kernel(const float* __restrict__ in,
                             __nv_bfloat16* __restrict__ h,
                             __nv_bfloat16* __restrict__ l, size_t n4) {
    size_t i = (size_t)blockIdx.x * blockDim.x + threadIdx.x;
    size_t stride = (size_t)gridDim.x * blockDim.x;
    for (; i < n4; i += stride) {
        float4 v = ((const float4*)in)[i];
        __nv_bfloat16 h0,l0,h1,l1,h2,l2,h3,l3;
        split_bf16(v.x, h0, l0); split_bf16(v.y, h1, l1);
        split_bf16(v.z, h2, l2); split_bf16(v.w, h3, l3);
        __nv_bfloat162 hh0(h0, h1), hh1(h2, h3), ll0(l0, l1), ll1(l2, l3);
        ((__nv_bfloat162*)h)[i * 2]     = hh0;
        ((__nv_bfloat162*)h)[i * 2 + 1] = hh1;
        ((__nv_bfloat162*)l)[i * 2]     = ll0;
        ((__nv_bfloat162*)l)[i * 2 + 1] = ll1;
    }
}

// ---------------------------------------------------------------------------
// Transpose + split: W[K][N] fp32 -> Wt hi/lo [N][K] bf16
// ---------------------------------------------------------------------------
__global__ void tsplit_kernel(const float* __restrict__ W,
                              __nv_bfloat16* __restrict__ th,
                              __nv_bfloat16* __restrict__ tl, int K, int N) {
    __shared__ float t[32][33];
    int n0 = blockIdx.x * 32, k0 = blockIdx.y * 32;
    int tx = threadIdx.x, ty = threadIdx.y;           // (32, 8)
    #pragma unroll
    for (int i = ty; i < 32; i += 8)
        t[i][tx] = W[(size_t)(k0 + i) * N + n0 + tx];
    __syncthreads();
    #pragma unroll
    for (int i = ty; i < 32; i += 8) {
        float v = t[tx][i];
        __nv_bfloat16 h, l;
        split_bf16(v, h, l);
        th[(size_t)(n0 + i) * K + k0 + tx] = h;
        tl[(size_t)(n0 + i) * K + k0 + tx] = l;
    }
}

// ---------------------------------------------------------------------------
// bf16x3 double-buffered cp.async GEMM (unchanged from round 4, verified).
// ---------------------------------------------------------------------------
#define BKK 64
#define PITCH 36
#define TILE_U32 (128 * PITCH)
#define STAGE_U32 (4 * TILE_U32)

__device__ __forceinline__ void cp16(unsigned smem_addr, const void* gptr) {
    asm volatile("cp.async.cg.shared.global [%0], [%1], 16;"
                 :: "r"(smem_addr), "l"(gptr));
}

__global__ __launch_bounds__(256)
void gemm_bf16x3_db(const __nv_bfloat16* __restrict__ Ah,
                    const __nv_bfloat16* __restrict__ Al,
                    const __nv_bfloat16* __restrict__ Bth,
                    const __nv_bfloat16* __restrict__ Btl,
                    const float* __restrict__ bias,
                    float* __restrict__ C, int Nz, int Kz) {
    extern __shared__ unsigned sm[];

    const int tid  = threadIdx.x;
    const int lane = tid & 31;
    const int wid  = tid >> 5;
    const int wm   = wid >> 2;
    const int wn   = wid & 3;
    const int g    = lane >> 2;
    const int tig  = lane & 3;

    const int rowBase = blockIdx.y * 128;
    const int colBase = blockIdx.x * 128;

    const int r0 = tid >> 3;
    const int c8 = tid & 7;

    const unsigned smem_base = (unsigned)__cvta_generic_to_shared(sm);

    float acc[4][4][4];
    #pragma unroll
    for (int i = 0; i < 4; i++)
        #pragma unroll
        for (int j = 0; j < 4; j++)
            #pragma unroll
            for (int q = 0; q < 4; q++) acc[i][j][q] = 0.0f;

    const int NIT = Kz / BKK;

    auto load_stage = [&](int it, int buf) {
        const int k0 = it * BKK;
        const unsigned sbase = smem_base + buf * STAGE_U32 * 4;
        #pragma unroll
        for (int it4 = 0; it4 < 4; it4++) {
            int row = r0 + it4 * 32;
            unsigned soff = (unsigned)(row * PITCH + c8 * 4) * 4;
            const __nv_bfloat16* gA = Ah + (size_t)(rowBase + row) * Kz + k0 + c8 * 8;
            const __nv_bfloat16* gAl2 = Al + (size_t)(rowBase + row) * Kz + k0 + c8 * 8;
            const __nv_bfloat16* gB = Bth + (size_t)(colBase + row) * Kz + k0 + c8 * 8;
            const __nv_bfloat16* gBl2 = Btl + (size_t)(colBase + row) * Kz + k0 + c8 * 8;
            cp16(sbase + soff, gA);
            cp16(sbase + TILE_U32 * 4 + soff, gAl2);
            cp16(sbase + 2 * TILE_U32 * 4 + soff, gB);
            cp16(sbase + 3 * TILE_U32 * 4 + soff, gBl2);
        }
        asm volatile("cp.async.commit_group;");
    };

    load_stage(0, 0);

    for (int it = 0; it < NIT; it++) {
        const int buf = it & 1;
        if (it + 1 < NIT) {
            load_stage(it + 1, (it + 1) & 1);
            asm volatile("cp.async.wait_group 1;");
        } else {
            asm volatile("cp.async.wait_group 0;");
        }
        __syncthreads();

        const unsigned* sAh = sm + buf * STAGE_U32;
        const unsigned* sAl = sAh + TILE_U32;
        const unsigned* sBh = sAh + 2 * TILE_U32;
        const unsigned* sBl = sAh + 3 * TILE_U32;

        #pragma unroll
        for (int kk8 = 0; kk8 < 4; kk8++) {
            const int pa = kk8 * 8 + tig;
            unsigned ahi[4][4], alo[4][4], bhi[4][2], blo[4][2];
            #pragma unroll
            for (int mi = 0; mi < 4; mi++) {
                int m0 = wm * 64 + mi * 16;
                ahi[mi][0] = sAh[(m0 + g) * PITCH + pa];
                ahi[mi][1] = sAh[(m0 + g + 8) * PITCH + pa];
                ahi[mi][2] = sAh[(m0 + g) * PITCH + pa + 4];
                ahi[mi][3] = sAh[(m0 + g + 8) * PITCH + pa + 4];
                alo[mi][0] = sAl[(m0 + g) * PITCH + pa];
                alo[mi][1] = sAl[(m0 + g + 8) * PITCH + pa];
                alo[mi][2] = sAl[(m0 + g) * PITCH + pa + 4];
                alo[mi][3] = sAl[(m0 + g + 8) * PITCH + pa + 4];
            }
            #pragma unroll
            for (int ni = 0; ni < 4; ni++) {
                int n0 = wn * 32 + ni * 8;
                bhi[ni][0] = sBh[(n0 + g) * PITCH + pa];
                bhi[ni][1] = sBh[(n0 + g) * PITCH + pa + 4];
                blo[ni][0] = sBl[(n0 + g) * PITCH + pa];
                blo[ni][1] = sBl[(n0 + g) * PITCH + pa + 4];
            }
            #pragma unroll
            for (int mi = 0; mi < 4; mi++)
                #pragma unroll
                for (int ni = 0; ni < 4; ni++) {
                    mma16816(acc[mi][ni], ahi[mi], bhi[ni]);
                    mma16816(acc[mi][ni], ahi[mi], blo[ni]);
                    mma16816(acc[mi][ni], alo[mi], bhi[ni]);
                }
        }
        __syncthreads();
    }

    #pragma unroll
    for (int mi = 0; mi < 4; mi++) {
        int row0 = rowBase + wm * 64 + mi * 16 + g;
        int row1 = row0 + 8;
        #pragma unroll
        for (int ni = 0; ni < 4; ni++) {
            int col = colBase + wn * 32 + ni * 8 + tig * 2;
            float b0 = __ldg(&bias[col]);
            float b1 = __ldg(&bias[col + 1]);
            C[(size_t)row0 * Nz + col]     = acc[mi][ni][0] + b0;
            C[(size_t)row0 * Nz + col + 1] = acc[mi][ni][1] + b1;
            C[(size_t)row1 * Nz + col]     = acc[mi][ni][2] + b0;
            C[(size_t)row1 * Nz + col + 1] = acc[mi][ni][3] + b1;
        }
    }
}

// ---------------------------------------------------------------------------
// Fused RMSNorm + bf16 hi/lo split: g_qkv q/k sections -> g_Qh/Ql/Kh/Kl.
// One warp per (row, head, which).
// ---------------------------------------------------------------------------
__global__ void rmsnorm_split_kernel(const float* __restrict__ wq,
                                     const float* __restrict__ wk) {
    int gw = (blockIdx.x * blockDim.x + threadIdx.x) >> 5;
    int lane = threadIdx.x & 31;
    int which = gw & 1;
    int head = (gw >> 1) & 15;
    int row = gw >> 5;
    if (row >= Mrows) return;

    const float* p = g_qkv + (size_t)row * N3 + which * Dn + head * DH;
    float2 v = ((const float2*)p)[lane];
    float ss = v.x * v.x + v.y * v.y;
    #pragma unroll
    for (int o = 16; o; o >>= 1) ss += __shfl_xor_sync(0xffffffffu, ss, o);
    float inv = rsqrtf(ss * (1.0f / DH) + 1e-6f);
    const float* w = which ? wk : wq;
    float2 wv = ((const float2*)w)[lane];
    float a0 = v.x * inv * wv.x;
    float a1 = v.y * inv * wv.y;

    __nv_bfloat16 h0, l0, h1, l1;
    split_bf16(a0, h0, l0);
    split_bf16(a1, h1, l1);
    size_t off = (size_t)row * Dn + head * DH;
    __nv_bfloat16* dh = (which ? g_Kh : g_Qh) + off;
    __nv_bfloat16* dl = (which ? g_Kl : g_Ql) + off;
    ((__nv_bfloat162*)dh)[lane] = __nv_bfloat162(h0, h1);
    ((__nv_bfloat162*)dl)[lane] = __nv_bfloat162(l0, l1);
}

// ---------------------------------------------------------------------------
// V transpose + split: g_qkv v section [b,s][h,d] -> g_Vth/Vtl [(b,h,d)][s]
// ---------------------------------------------------------------------------
__global__ void vsplit_kernel() {
    __shared__ float t[64][65];
    int s0 = blockIdx.x * 64;
    int h = blockIdx.y, b = blockIdx.z;
    int tid = threadIdx.x;
    #pragma unroll
    for (int it = 0; it < 16; it++) {
        int idx = tid + it * 256;
        int sr = idx >> 6, d = idx & 63;
        t[sr][d] = g_qkv[((size_t)b * Sn + s0 + sr) * N3 + 2 * Dn + h * DH + d];
    }
    __syncthreads();
    #pragma unroll
    for (int it = 0; it < 16; it++) {
        int idx = tid + it * 256;
        int d = idx >> 6, sc = idx & 63;
        float v = t[sc][d];
        __nv_bfloat16 hh, ll;
        split_bf16(v, hh, ll);
        size_t off = ((size_t)(b * NH + h) * DH + d) * Sn + s0 + sc;
        g_Vth[off] = hh;
        g_Vtl[off] = ll;
    }
}

// ---------------------------------------------------------------------------
// Flash attention with bf16x3 MMA.
// Block = (b, h, 64 q rows), 128 threads = 4 warps (16 q-rows each).
// S = Q@K^T (3 MMAs/frag), online softmax on fragments, P split in regs,
// O += P@V (3 MMAs/frag). Smem tiles pitch-36 u32 (conflict-free).
// ---------------------------------------------------------------------------
#define AP 36
#define ATILE (64 * AP)

__global__ __launch_bounds__(128) void attn_mma_kernel() {
    extern __shared__ unsigned smu[];
    unsigned* sQh = smu;
    unsigned* sQl = sQh + ATILE;
    unsigned* sKh = sQl + ATILE;
    unsigned* sKl = sKh + ATILE;
    unsigned* sVh = sKl + ATILE;
    unsigned* sVl = sVh + ATILE;

    const int tid  = threadIdx.x;
    const int lane = tid & 31;
    const int w    = tid >> 5;         // warp 0..3
    const int g    = lane >> 2;
    const int tig  = lane & 3;

    const int qt = gridDim.x - 1 - blockIdx.x;   // big tiles first
    const int h  = blockIdx.y;
    const int b  = blockIdx.z;

    const size_t rowQ0 = (size_t)b * Sn + qt * 64;
    const size_t qk_off = h * DH;      // within [row][Dn]
    const size_t v_row0 = (size_t)(b * NH + h) * DH;   // Vt row base

    // Load Q tile (64 rows x 64 d) hi/lo: 512 uint4 per matrix, 128 thr x 4
    #pragma unroll
    for (int it = 0; it < 4; it++) {
        int idx = tid + it * 128;      // 0..511
        int r = idx >> 3, q4 = idx & 7;
        const uint4* gh = (const uint4*)(g_Qh + (rowQ0 + r) * Dn + qk_off);
        const uint4* gl = (const uint4*)(g_Ql + (rowQ0 + r) * Dn + qk_off);
        ((uint4*)(sQh + r * AP))[q4] = gh[q4];
        ((uint4*)(sQl + r * AP))[q4] = gl[q4];
    }

    float o[8][4];
    #pragma unroll
    for (int ni = 0; ni < 8; ni++)
        #pragma unroll
        for (int c = 0; c < 4; c++) o[ni][c] = 0.0f;
    float m0 = -INFINITY, m1 = -INFINITY, l0 = 0.0f, l1 = 0.0f;

    __syncthreads();

    for (int kt = 0; kt <= qt; kt++) {
        const size_t rowK0 = (size_t)b * Sn + kt * 64;
        // Load K tile (rows=seq, k=d) and Vt tile (rows=d, k=seq) hi/lo
        #pragma unroll
        for (int it = 0; it < 4; it++) {
            int idx = tid + it * 128;
            int r = idx >> 3, q4 = idx & 7;
            const uint4* kh = (const uint4*)(g_Kh + (rowK0 + r) * Dn + qk_off);
            const uint4* kl = (const uint4*)(g_Kl + (rowK0 + r) * Dn + qk_off);
            ((uint4*)(sKh + r * AP))[q4] = kh[q4];
            ((uint4*)(sKl + r * AP))[q4] = kl[q4];
            const uint4* vh = (const uint4*)(g_Vth + (v_row0 + r) * Sn + kt * 64);
            const uint4* vl = (const uint4*)(g_Vtl + (v_row0 + r) * Sn + kt * 64);
            ((uint4*)(sVh + r * AP))[q4] = vh[q4];
            ((uint4*)(sVl + r * AP))[q4] = vl[q4];
        }
        __syncthreads();

        // ---- S = Q @ K^T ----
        float s[8][4];
        #pragma unroll
        for (int ni = 0; ni < 8; ni++)
            #pragma unroll
            for (int c = 0; c < 4; c++) s[ni][c] = 0.0f;

        const int m0r = w * 16;
        #pragma unroll
        for (int kk = 0; kk < 4; kk++) {
            const int pa = kk * 8 + tig;
            unsigned ah[4], al[4];
            ah[0] = sQh[(m0r + g) * AP + pa];
            ah[1] = sQh[(m0r + g + 8) * AP + pa];
            ah[2] = sQh[(m0r + g) * AP + pa + 4];
            ah[3] = sQh[(m0r + g + 8) * AP + pa + 4];
            al[0] = sQl[(m0r + g) * AP + pa];
            al[1] = sQl[(m0r + g + 8) * AP + pa];
            al[2] = sQl[(m0r + g) * AP + pa + 4];
            al[3] = sQl[(m0r + g + 8) * AP + pa + 4];
            #pragma unroll
            for (int ni = 0; ni < 8; ni++) {
                unsigned bh[2], bl[2];
                bh[0] = sKh[(ni * 8 + g) * AP + pa];
                bh[1] = sKh[(ni * 8 + g) * AP + pa + 4];
                bl[0] = sKl[(ni * 8 + g) * AP + pa];
                bl[1] = sKl[(ni * 8 + g) * AP + pa + 4];
                mma16816(s[ni], ah, bh);
                mma16816(s[ni], ah, bl);
                mma16816(s[ni], al, bh);
            }
        }

        // ---- causal mask on diagonal tile ----
        if (kt == qt) {
            #pragma unroll
            for (int ni = 0; ni < 8; ni++) {
                int col = ni * 8 + 2 * tig;
                int r0 = m0r + g, r1 = r0 + 8;
                if (col > r0)     s[ni][0] = -INFINITY;
                if (col + 1 > r0) s[ni][1] = -INFINITY;
                if (col > r1)     s[ni][2] = -INFINITY;
                if (col + 1 > r1) s[ni][3] = -INFINITY;
            }
        }

        // ---- online softmax (rows g and g+8; quad = same g, tig 0..3) ----
        float rm0 = -INFINITY, rm1 = -INFINITY;
        #pragma unroll
        for (int ni = 0; ni < 8; ni++) {
            rm0 = fmaxf(rm0, fmaxf(s[ni][0], s[ni][1]));
            rm1 = fmaxf(rm1, fmaxf(s[ni][2], s[ni][3]));
        }
        rm0 = fmaxf(rm0, __shfl_xor_sync(0xffffffffu, rm0, 1));
        rm0 = fmaxf(rm0, __shfl_xor_sync(0xffffffffu, rm0, 2));
        rm1 = fmaxf(rm1, __shfl_xor_sync(0xffffffffu, rm1, 1));
        rm1 = fmaxf(rm1, __shfl_xor_sync(0xffffffffu, rm1, 2));
        float mn0 = fmaxf(m0, rm0), mn1 = fmaxf(m1, rm1);

        float rs0 = 0.0f, rs1 = 0.0f;
        #pragma unroll
        for (int ni = 0; ni < 8; ni++) {
            s[ni][0] = __expf(s[ni][0] - mn0);
            s[ni][1] = __expf(s[ni][1] - mn0);
            s[ni][2] = __expf(s[ni][2] - mn1);
            s[ni][3] = __expf(s[ni][3] - mn1);
            rs0 += s[ni][0] + s[ni][1];
            rs1 += s[ni][2] + s[ni][3];
        }
        rs0 += __shfl_xor_sync(0xffffffffu, rs0, 1);
        rs0 += __shfl_xor_sync(0xffffffffu, rs0, 2);
        rs1 += __shfl_xor_sync(0xffffffffu, rs1, 1);
        rs1 += __shfl_xor_sync(0xffffffffu, rs1, 2);

        float al0 = __expf(m0 - mn0), al1 = __expf(m1 - mn1);
        l0 = l0 * al0 + rs0;
        l1 = l1 * al1 + rs1;
        m0 = mn0; m1 = mn1;
        #pragma unroll
        for (int ni = 0; ni < 8; ni++) {
            o[ni][0] *= al0; o[ni][1] *= al0;
            o[ni][2] *= al1; o[ni][3] *= al1;
        }

        // ---- O += P @ V  (P from s fragments, split hi/lo in regs) ----
        #pragma unroll
        for (int kk = 0; kk < 4; kk++) {
            unsigned pah[4], pal[4];
            {
                __nv_bfloat16 h00,l00,h01,l01,h10,l10,h11,l11;
                split_bf16(s[2*kk][0], h00, l00);
                split_bf16(s[2*kk][1], h01, l01);
                split_bf16(s[2*kk][2], h10, l10);
                split_bf16(s[2*kk][3], h11, l11);
                pah[0] = pack2(h00, h01); pal[0] = pack2(l00, l01);
                pah[1] = pack2(h10, h11); pal[1] = pack2(l10, l11);
                split_bf16(s[2*kk+1][0], h00, l00);
                split_bf16(s[2*kk+1][1], h01, l01);
                split_bf16(s[2*kk+1][2], h10, l10);
                split_bf16(s[2*kk+1][3], h11, l11);
                pah[2] = pack2(h00, h01); pal[2] = pack2(l00, l01);
                pah[3] = pack2(h10, h11); pal[3] = pack2(l10, l11);
            }
            const int pa = kk * 8 + tig;
            #pragma unroll
            for (int ni = 0; ni < 8; ni++) {
                unsigned vh[2], vl[2];
                vh[0] = sVh[(ni * 8 + g) * AP + pa];
                vh[1] = sVh[(ni * 8 + g) * AP + pa + 4];
                vl[0] = sVl[(ni * 8 + g) * AP + pa];
                vl[1] = sVl[(ni * 8 + g) * AP + pa + 4];
                mma16816(o[ni], pah, vh);
                mma16816(o[ni], pah, vl);
                mma16816(o[ni], pal, vh);
            }
        }
        __syncthreads();
    }

    // ---- finalize: z = O / l ----
    float inv0 = 1.0f / l0, inv1 = 1.0f / l1;
    size_t row0 = rowQ0 + w * 16 + g;
    size_t row1 = row0 + 8;
    #pragma unroll
    for (int ni = 0; ni < 8; ni++) {
        int col = h * DH + ni * 8 + 2 * tig;
        *(float2*)&g_z[row0 * Dn + col] = make_float2(o[ni][0] * inv0, o[ni][1] * inv0);
        *(float2*)&g_z[row1 * Dn + col] = make_float2(o[ni][2] * inv1, o[ni][3] * inv1);
    }
}

// ---------------------------------------------------------------------------
extern "C" void kernel_launch(void* const* d_in, const int* in_sizes, int n_in,
                              void* d_out, int out_size) {
    const float* x     = (const float*)d_in[0];
    const float* W_qkv = (const float*)d_in[2];
    const float* b_qkv = (const float*)d_in[3];
    const float* W_o   = (const float*)d_in[4];
    const float* b_o   = (const float*)d_in[5];
    const float* wq    = (const float*)d_in[6];
    const float* wk    = (const float*)d_in[7];
    float* out = (float*)d_out;

    void *qkv_ptr, *z_ptr, *ah, *al, *wth, *wtl, *woth, *wotl;
    cudaGetSymbolAddress(&qkv_ptr, g_qkv);
    cudaGetSymbolAddress(&z_ptr, g_z);
    cudaGetSymbolAddress(&ah, g_Ah);
    cudaGetSymbolAddress(&al, g_Al);
    cudaGetSymbolAddress(&wth, g_Wth);
    cudaGetSymbolAddress(&wtl, g_Wtl);
    cudaGetSymbolAddress(&woth, g_Woth);
    cudaGetSymbolAddress(&wotl, g_Wotl);

    const int gemm_smem = 2 * STAGE_U32 * 4;   // 147456 B
    cudaFuncSetAttribute(gemm_bf16x3_db,
                         cudaFuncAttributeMaxDynamicSharedMemorySize, gemm_smem);
    const int attn_smem = 6 * ATILE * 4;       // 55296 B
    cudaFuncSetAttribute(attn_mma_kernel,
                         cudaFuncAttributeMaxDynamicSharedMemorySize, attn_smem);

    // 0) Preprocessing: split x; transpose+split weights
    split_kernel<<<1024, 256>>>(x, (__nv_bfloat16*)ah, (__nv_bfloat16*)al,
                                (size_t)Mrows * Dn / 4);
    {
        dim3 grid(N3 / 32, Dn / 32);
        tsplit_kernel<<<grid, dim3(32, 8)>>>(W_qkv, (__nv_bfloat16*)wth,
                                             (__nv_bfloat16*)wtl, Dn, N3);
    }
    {
        dim3 grid(Dn / 32, Dn / 32);
        tsplit_kernel<<<grid, dim3(32, 8)>>>(W_o, (__nv_bfloat16*)woth,
                                             (__nv_bfloat16*)wotl, Dn, Dn);
    }

    // 1) QKV GEMM
    {
        dim3 grid(N3 / 128, Mrows / 128);
        gemm_bf16x3_db<<<grid, 256, gemm_smem>>>(
            (const __nv_bfloat16*)ah, (const __nv_bfloat16*)al,
            (const __nv_bfloat16*)wth, (const __nv_bfloat16*)wtl,
            b_qkv, (float*)qkv_ptr, N3, Dn);
    }

    // 2) RMSNorm + split q,k; transpose-split v
    {
        int total_warps = Mrows * NH * 2;
        int blocks = (total_warps * 32) / 256;
        rmsnorm_split_kernel<<<blocks, 256>>>(wq, wk);
    }
    {
        dim3 grid(Sn / 64, NH, Bn);
        vsplit_kernel<<<grid, 256>>>();
    }

    // 3) Flash attention (bf16x3 MMA)
    {
        dim3 grid(Sn / 64, NH, Bn);
        attn_mma_kernel<<<grid, 128, attn_smem>>>();
    }

    // 4) Split z, then output projection
    split_kernel<<<1024, 256>>>((const float*)z_ptr, (__nv_bfloat16*)ah,
                                (__nv_bfloat16*)al, (size_t)Mrows * Dn / 4);
    {
        dim3 grid(Dn / 128, Mrows / 128);
        gemm_bf16x3_db<<<grid, 256, gemm_smem>>>(
            (const __nv_bfloat16*)ah, (const __nv_bfloat16*)al,
            (const __nv_bfloat16*)woth, (const __nv_bfloat16*)wotl,
            b_o, out, Dn, Dn);
    }
}

// round 7
// speedup vs baseline: 3.3310x; 1.5279x over previous
#include <cuda_runtime.h>
#include <cuda_bf16.h>
#include <math.h>
#include <stdint.h>

#define Bn 4
#define Sn 2048
#define Dn 1024
#define NH 16
#define DH 64
#define Mrows (Bn*Sn)      // 8192
#define N3 (3*Dn)          // 3072

// Scratch (device globals: allocation-free per harness rules)
__device__ float g_qkv[(size_t)Mrows * N3];            // 96 MB
__device__ __nv_bfloat16 g_Ah[(size_t)Mrows * Dn];     // x split hi / attn-out hi
__device__ __nv_bfloat16 g_Al[(size_t)Mrows * Dn];
__device__ __nv_bfloat16 g_Wth[(size_t)N3 * Dn];       // W_qkv^T hi [N][K]
__device__ __nv_bfloat16 g_Wtl[(size_t)N3 * Dn];
__device__ __nv_bfloat16 g_Woth[(size_t)Dn * Dn];      // W_o^T hi
__device__ __nv_bfloat16 g_Wotl[(size_t)Dn * Dn];
__device__ __nv_bfloat16 g_Qh[(size_t)Mrows * Dn];     // rmsnormed q split
__device__ __nv_bfloat16 g_Ql[(size_t)Mrows * Dn];
__device__ __nv_bfloat16 g_Kh[(size_t)Mrows * Dn];     // rmsnormed k split
__device__ __nv_bfloat16 g_Kl[(size_t)Mrows * Dn];
__device__ __nv_bfloat16 g_Vth[(size_t)Mrows * Dn];    // V^T split: [(b*NH+h)*DH+d][s]
__device__ __nv_bfloat16 g_Vtl[(size_t)Mrows * Dn];

__device__ __forceinline__ void split_bf16(float x, __nv_bfloat16& h, __nv_bfloat16& l) {
    h = __float2bfloat16_rn(x);
    l = __float2bfloat16_rn(x - __bfloat162float(h));
}
__device__ __forceinline__ unsigned pack2(__nv_bfloat16 lo, __nv_bfloat16 hi) {
    __nv_bfloat162 p(lo, hi);
    return *(unsigned*)&p;
}
__device__ __forceinline__ void mma16816(float* c, const unsigned* a, const unsigned* b) {
    asm volatile(
        "mma.sync.aligned.m16n8k16.row.col.f32.bf16.bf16.f32 "
        "{%0,%1,%2,%3}, {%4,%5,%6,%7}, {%8,%9}, {%0,%1,%2,%3};"
        : "+f"(c[0]), "+f"(c[1]), "+f"(c[2]), "+f"(c[3])
        : "r"(a[0]), "r"(a[1]), "r"(a[2]), "r"(a[3]), "r"(b[0]), "r"(b[1]));
}
__device__ __forceinline__ void cp16(unsigned smem_addr, const void* gptr) {
    asm volatile("cp.async.cg.shared.global [%0], [%1], 16;"
                 :: "r"(smem_addr), "l"(gptr));
}

// ---------------------------------------------------------------------------
// Elementwise split: fp32 -> (hi, lo) bf16
// ---------------------------------------------------------------------------
__global__ void split_kernel(const float* __restrict__ in,
                             __nv_bfloat16* __restrict__ h,
                             __nv_bfloat16* __restrict__ l, size_t n4) {
    size_t i = (size_t)blockIdx.x * blockDim.x + threadIdx.x;
    size_t stride = (size_t)gridDim.x * blockDim.x;
    for (; i < n4; i += stride) {
        float4 v = ((const float4*)in)[i];
        __nv_bfloat16 h0,l0,h1,l1,h2,l2,h3,l3;
        split_bf16(v.x, h0, l0); split_bf16(v.y, h1, l1);
        split_bf16(v.z, h2, l2); split_bf16(v.w, h3, l3);
        __nv_bfloat162 hh0(h0, h1), hh1(h2, h3), ll0(l0, l1), ll1(l2, l3);
        ((__nv_bfloat162*)h)[i * 2]     = hh0;
        ((__nv_bfloat162*)h)[i * 2 + 1] = hh1;
        ((__nv_bfloat162*)l)[i * 2]     = ll0;
        ((__nv_bfloat162*)l)[i * 2 + 1] = ll1;
    }
}

// ---------------------------------------------------------------------------
// Transpose + split: W[K][N] fp32 -> Wt hi/lo [N][K] bf16
// ---------------------------------------------------------------------------
__global__ void tsplit_kernel(const float* __restrict__ W,
                              __nv_bfloat16* __restrict__ th,
                              __nv_bfloat16* __restrict__ tl, int K, int N) {
    __shared__ float t[32][33];
    int n0 = blockIdx.x * 32, k0 = blockIdx.y * 32;
    int tx = threadIdx.x, ty = threadIdx.y;           // (32, 8)
    #pragma unroll
    for (int i = ty; i < 32; i += 8)
        t[i][tx] = W[(size_t)(k0 + i) * N + n0 + tx];
    __syncthreads();
    #pragma unroll
    for (int i = ty; i < 32; i += 8) {
        float v = t[tx][i];
        __nv_bfloat16 h, l;
        split_bf16(v, h, l);
        th[(size_t)(n0 + i) * K + k0 + tx] = h;
        tl[(size_t)(n0 + i) * K + k0 + tx] = l;
    }
}

// ---------------------------------------------------------------------------
// bf16x3 double-buffered cp.async GEMM, BK=32 / pitch-20 for 2 CTAs/SM.
// A: hi/lo bf16 [M][K]; Bt: hi/lo bf16 [N][K]; C = A@B + bias (fp32 out).
// 128x128 blocktile, 256 threads = 8 warps (2m x 4n).
// Per stage: 4 tiles x 128 rows x 20 u32 = 40 KB; 2 stages = 80 KB.
// ---------------------------------------------------------------------------
#define BKK 32
#define PITCH 20                       // 16 data u32 + 4 pad (conflict-free)
#define TILE_U32 (128 * PITCH)
#define STAGE_U32 (4 * TILE_U32)

__global__ __launch_bounds__(256, 2)
void gemm_bf16x3_db(const __nv_bfloat16* __restrict__ Ah,
                    const __nv_bfloat16* __restrict__ Al,
                    const __nv_bfloat16* __restrict__ Bth,
                    const __nv_bfloat16* __restrict__ Btl,
                    const float* __restrict__ bias,
                    float* __restrict__ C, int Nz, int Kz) {
    extern __shared__ unsigned sm[];

    const int tid  = threadIdx.x;
    const int lane = tid & 31;
    const int wid  = tid >> 5;
    const int wm   = wid >> 2;
    const int wn   = wid & 3;
    const int g    = lane >> 2;
    const int tig  = lane & 3;

    const int rowBase = blockIdx.y * 128;
    const int colBase = blockIdx.x * 128;

    // cp.async mapping: per tile 512 sectors (128 rows x 4 x 16B); 2 per thread
    const int r0 = tid >> 2;           // row for it2=0 (0..63), +64 for it2=1
    const int c4 = tid & 3;            // 16B sector in row

    const unsigned smem_base = (unsigned)__cvta_generic_to_shared(sm);

    float acc[4][4][4];
    #pragma unroll
    for (int i = 0; i < 4; i++)
        #pragma unroll
        for (int j = 0; j < 4; j++)
            #pragma unroll
            for (int q = 0; q < 4; q++) acc[i][j][q] = 0.0f;

    const int NIT = Kz / BKK;

    auto load_stage = [&](int it, int buf) {
        const int k0 = it * BKK;
        const unsigned sbase = smem_base + buf * STAGE_U32 * 4;
        #pragma unroll
        for (int it2 = 0; it2 < 2; it2++) {
            int row = r0 + it2 * 64;
            unsigned soff = (unsigned)(row * PITCH + c4 * 4) * 4;
            const __nv_bfloat16* gA   = Ah  + (size_t)(rowBase + row) * Kz + k0 + c4 * 8;
            const __nv_bfloat16* gAl2 = Al  + (size_t)(rowBase + row) * Kz + k0 + c4 * 8;
            const __nv_bfloat16* gB   = Bth + (size_t)(colBase + row) * Kz + k0 + c4 * 8;
            const __nv_bfloat16* gBl2 = Btl + (size_t)(colBase + row) * Kz + k0 + c4 * 8;
            cp16(sbase + soff, gA);
            cp16(sbase + TILE_U32 * 4 + soff, gAl2);
            cp16(sbase + 2 * TILE_U32 * 4 + soff, gB);
            cp16(sbase + 3 * TILE_U32 * 4 + soff, gBl2);
        }
        asm volatile("cp.async.commit_group;");
    };

    load_stage(0, 0);

    for (int it = 0; it < NIT; it++) {
        const int buf = it & 1;
        if (it + 1 < NIT) {
            load_stage(it + 1, (it + 1) & 1);
            asm volatile("cp.async.wait_group 1;");
        } else {
            asm volatile("cp.async.wait_group 0;");
        }
        __syncthreads();

        const unsigned* sAh = sm + buf * STAGE_U32;
        const unsigned* sAl = sAh + TILE_U32;
        const unsigned* sBh = sAh + 2 * TILE_U32;
        const unsigned* sBl = sAh + 3 * TILE_U32;

        #pragma unroll
        for (int kk8 = 0; kk8 < 2; kk8++) {
            const int pa = kk8 * 8 + tig;
            unsigned ahi[4][4], alo[4][4], bhi[4][2], blo[4][2];
            #pragma unroll
            for (int mi = 0; mi < 4; mi++) {
                int m0 = wm * 64 + mi * 16;
                ahi[mi][0] = sAh[(m0 + g) * PITCH + pa];
                ahi[mi][1] = sAh[(m0 + g + 8) * PITCH + pa];
                ahi[mi][2] = sAh[(m0 + g) * PITCH + pa + 4];
                ahi[mi][3] = sAh[(m0 + g + 8) * PITCH + pa + 4];
                alo[mi][0] = sAl[(m0 + g) * PITCH + pa];
                alo[mi][1] = sAl[(m0 + g + 8) * PITCH + pa];
                alo[mi][2] = sAl[(m0 + g) * PITCH + pa + 4];
                alo[mi][3] = sAl[(m0 + g + 8) * PITCH + pa + 4];
            }
            #pragma unroll
            for (int ni = 0; ni < 4; ni++) {
                int n0 = wn * 32 + ni * 8;
                bhi[ni][0] = sBh[(n0 + g) * PITCH + pa];
                bhi[ni][1] = sBh[(n0 + g) * PITCH + pa + 4];
                blo[ni][0] = sBl[(n0 + g) * PITCH + pa];
                blo[ni][1] = sBl[(n0 + g) * PITCH + pa + 4];
            }
            #pragma unroll
            for (int mi = 0; mi < 4; mi++)
                #pragma unroll
                for (int ni = 0; ni < 4; ni++) {
                    mma16816(acc[mi][ni], ahi[mi], bhi[ni]);
                    mma16816(acc[mi][ni], ahi[mi], blo[ni]);
                    mma16816(acc[mi][ni], alo[mi], bhi[ni]);
                }
        }
        __syncthreads();
    }

    #pragma unroll
    for (int mi = 0; mi < 4; mi++) {
        int row0 = rowBase + wm * 64 + mi * 16 + g;
        int row1 = row0 + 8;
        #pragma unroll
        for (int ni = 0; ni < 4; ni++) {
            int col = colBase + wn * 32 + ni * 8 + tig * 2;
            float b0 = __ldg(&bias[col]);
            float b1 = __ldg(&bias[col + 1]);
            C[(size_t)row0 * Nz + col]     = acc[mi][ni][0] + b0;
            C[(size_t)row0 * Nz + col + 1] = acc[mi][ni][1] + b1;
            C[(size_t)row1 * Nz + col]     = acc[mi][ni][2] + b0;
            C[(size_t)row1 * Nz + col + 1] = acc[mi][ni][3] + b1;
        }
    }
}

// ---------------------------------------------------------------------------
// Fused RMSNorm + bf16 hi/lo split: g_qkv q/k sections -> g_Qh/Ql/Kh/Kl.
// ---------------------------------------------------------------------------
__global__ void rmsnorm_split_kernel(const float* __restrict__ wq,
                                     const float* __restrict__ wk) {
    int gw = (blockIdx.x * blockDim.x + threadIdx.x) >> 5;
    int lane = threadIdx.x & 31;
    int which = gw & 1;
    int head = (gw >> 1) & 15;
    int row = gw >> 5;
    if (row >= Mrows) return;

    const float* p = g_qkv + (size_t)row * N3 + which * Dn + head * DH;
    float2 v = ((const float2*)p)[lane];
    float ss = v.x * v.x + v.y * v.y;
    #pragma unroll
    for (int o = 16; o; o >>= 1) ss += __shfl_xor_sync(0xffffffffu, ss, o);
    float inv = rsqrtf(ss * (1.0f / DH) + 1e-6f);
    const float* w = which ? wk : wq;
    float2 wv = ((const float2*)w)[lane];
    float a0 = v.x * inv * wv.x;
    float a1 = v.y * inv * wv.y;

    __nv_bfloat16 h0, l0, h1, l1;
    split_bf16(a0, h0, l0);
    split_bf16(a1, h1, l1);
    size_t off = (size_t)row * Dn + head * DH;
    __nv_bfloat16* dh = (which ? g_Kh : g_Qh) + off;
    __nv_bfloat16* dl = (which ? g_Kl : g_Ql) + off;
    ((__nv_bfloat162*)dh)[lane] = __nv_bfloat162(h0, h1);
    ((__nv_bfloat162*)dl)[lane] = __nv_bfloat162(l0, l1);
}

// ---------------------------------------------------------------------------
// V transpose + split: g_qkv v section [b,s][h,d] -> g_Vth/Vtl [(b,h,d)][s]
// ---------------------------------------------------------------------------
__global__ void vsplit_kernel() {
    __shared__ float t[64][65];
    int s0 = blockIdx.x * 64;
    int h = blockIdx.y, b = blockIdx.z;
    int tid = threadIdx.x;
    #pragma unroll
    for (int it = 0; it < 16; it++) {
        int idx = tid + it * 256;
        int sr = idx >> 6, d = idx & 63;
        t[sr][d] = g_qkv[((size_t)b * Sn + s0 + sr) * N3 + 2 * Dn + h * DH + d];
    }
    __syncthreads();
    #pragma unroll
    for (int it = 0; it < 16; it++) {
        int idx = tid + it * 256;
        int d = idx >> 6, sc = idx & 63;
        float v = t[sc][d];
        __nv_bfloat16 hh, ll;
        split_bf16(v, hh, ll);
        size_t off = ((size_t)(b * NH + h) * DH + d) * Sn + s0 + sc;
        g_Vth[off] = hh;
        g_Vtl[off] = ll;
    }
}

// ---------------------------------------------------------------------------
// Flash attention with bf16x3 mma.sync (round-5 verified), with the output
// hi/lo split fused into the epilogue (writes g_Ah/g_Al directly).
// ---------------------------------------------------------------------------
#define AP 36
#define ATILE (64 * AP)

__global__ __launch_bounds__(128) void attn_mma_kernel() {
    extern __shared__ unsigned smu[];
    unsigned* sQh = smu;
    unsigned* sQl = sQh + ATILE;
    unsigned* sKh = sQl + ATILE;
    unsigned* sKl = sKh + ATILE;
    unsigned* sVh = sKl + ATILE;
    unsigned* sVl = sVh + ATILE;

    const int tid  = threadIdx.x;
    const int lane = tid & 31;
    const int w    = tid >> 5;
    const int g    = lane >> 2;
    const int tig  = lane & 3;

    const int qt = gridDim.x - 1 - blockIdx.x;
    const int h  = blockIdx.y;
    const int b  = blockIdx.z;

    const size_t rowQ0 = (size_t)b * Sn + qt * 64;
    const size_t qk_off = h * DH;
    const size_t v_row0 = (size_t)(b * NH + h) * DH;

    #pragma unroll
    for (int it = 0; it < 4; it++) {
        int idx = tid + it * 128;
        int r = idx >> 3, q4 = idx & 7;
        const uint4* gh = (const uint4*)(g_Qh + (rowQ0 + r) * Dn + qk_off);
        const uint4* gl = (const uint4*)(g_Ql + (rowQ0 + r) * Dn + qk_off);
        ((uint4*)(sQh + r * AP))[q4] = gh[q4];
        ((uint4*)(sQl + r * AP))[q4] = gl[q4];
    }

    float o[8][4];
    #pragma unroll
    for (int ni = 0; ni < 8; ni++)
        #pragma unroll
        for (int c = 0; c < 4; c++) o[ni][c] = 0.0f;
    float m0 = -INFINITY, m1 = -INFINITY, l0 = 0.0f, l1 = 0.0f;

    __syncthreads();

    for (int kt = 0; kt <= qt; kt++) {
        const size_t rowK0 = (size_t)b * Sn + kt * 64;
        #pragma unroll
        for (int it = 0; it < 4; it++) {
            int idx = tid + it * 128;
            int r = idx >> 3, q4 = idx & 7;
            const uint4* kh = (const uint4*)(g_Kh + (rowK0 + r) * Dn + qk_off);
            const uint4* kl = (const uint4*)(g_Kl + (rowK0 + r) * Dn + qk_off);
            ((uint4*)(sKh + r * AP))[q4] = kh[q4];
            ((uint4*)(sKl + r * AP))[q4] = kl[q4];
            const uint4* vh = (const uint4*)(g_Vth + (v_row0 + r) * Sn + kt * 64);
            const uint4* vl = (const uint4*)(g_Vtl + (v_row0 + r) * Sn + kt * 64);
            ((uint4*)(sVh + r * AP))[q4] = vh[q4];
            ((uint4*)(sVl + r * AP))[q4] = vl[q4];
        }
        __syncthreads();

        float s[8][4];
        #pragma unroll
        for (int ni = 0; ni < 8; ni++)
            #pragma unroll
            for (int c = 0; c < 4; c++) s[ni][c] = 0.0f;

        const int m0r = w * 16;
        #pragma unroll
        for (int kk = 0; kk < 4; kk++) {
            const int pa = kk * 8 + tig;
            unsigned ah[4], al[4];
            ah[0] = sQh[(m0r + g) * AP + pa];
            ah[1] = sQh[(m0r + g + 8) * AP + pa];
            ah[2] = sQh[(m0r + g) * AP + pa + 4];
            ah[3] = sQh[(m0r + g + 8) * AP + pa + 4];
            al[0] = sQl[(m0r + g) * AP + pa];
            al[1] = sQl[(m0r + g + 8) * AP + pa];
            al[2] = sQl[(m0r + g) * AP + pa + 4];
            al[3] = sQl[(m0r + g + 8) * AP + pa + 4];
            #pragma unroll
            for (int ni = 0; ni < 8; ni++) {
                unsigned bh[2], bl[2];
                bh[0] = sKh[(ni * 8 + g) * AP + pa];
                bh[1] = sKh[(ni * 8 + g) * AP + pa + 4];
                bl[0] = sKl[(ni * 8 + g) * AP + pa];
                bl[1] = sKl[(ni * 8 + g) * AP + pa + 4];
                mma16816(s[ni], ah, bh);
                mma16816(s[ni], ah, bl);
                mma16816(s[ni], al, bh);
            }
        }

        if (kt == qt) {
            #pragma unroll
            for (int ni = 0; ni < 8; ni++) {
                int col = ni * 8 + 2 * tig;
                int r0 = m0r + g, r1 = r0 + 8;
                if (col > r0)     s[ni][0] = -INFINITY;
                if (col + 1 > r0) s[ni][1] = -INFINITY;
                if (col > r1)     s[ni][2] = -INFINITY;
                if (col + 1 > r1) s[ni][3] = -INFINITY;
            }
        }

        float rm0 = -INFINITY, rm1 = -INFINITY;
        #pragma unroll
        for (int ni = 0; ni < 8; ni++) {
            rm0 = fmaxf(rm0, fmaxf(s[ni][0], s[ni][1]));
            rm1 = fmaxf(rm1, fmaxf(s[ni][2], s[ni][3]));
        }
        rm0 = fmaxf(rm0, __shfl_xor_sync(0xffffffffu, rm0, 1));
        rm0 = fmaxf(rm0, __shfl_xor_sync(0xffffffffu, rm0, 2));
        rm1 = fmaxf(rm1, __shfl_xor_sync(0xffffffffu, rm1, 1));
        rm1 = fmaxf(rm1, __shfl_xor_sync(0xffffffffu, rm1, 2));
        float mn0 = fmaxf(m0, rm0), mn1 = fmaxf(m1, rm1);

        float rs0 = 0.0f, rs1 = 0.0f;
        #pragma unroll
        for (int ni = 0; ni < 8; ni++) {
            s[ni][0] = __expf(s[ni][0] - mn0);
            s[ni][1] = __expf(s[ni][1] - mn0);
            s[ni][2] = __expf(s[ni][2] - mn1);
            s[ni][3] = __expf(s[ni][3] - mn1);
            rs0 += s[ni][0] + s[ni][1];
            rs1 += s[ni][2] + s[ni][3];
        }
        rs0 += __shfl_xor_sync(0xffffffffu, rs0, 1);
        rs0 += __shfl_xor_sync(0xffffffffu, rs0, 2);
        rs1 += __shfl_xor_sync(0xffffffffu, rs1, 1);
        rs1 += __shfl_xor_sync(0xffffffffu, rs1, 2);

        float al0 = __expf(m0 - mn0), al1 = __expf(m1 - mn1);
        l0 = l0 * al0 + rs0;
        l1 = l1 * al1 + rs1;
        m0 = mn0; m1 = mn1;
        #pragma unroll
        for (int ni = 0; ni < 8; ni++) {
            o[ni][0] *= al0; o[ni][1] *= al0;
            o[ni][2] *= al1; o[ni][3] *= al1;
        }

        #pragma unroll
        for (int kk = 0; kk < 4; kk++) {
            unsigned pah[4], pal[4];
            {
                __nv_bfloat16 h00,l00,h01,l01,h10,l10,h11,l11;
                split_bf16(s[2*kk][0], h00, l00);
                split_bf16(s[2*kk][1], h01, l01);
                split_bf16(s[2*kk][2], h10, l10);
                split_bf16(s[2*kk][3], h11, l11);
                pah[0] = pack2(h00, h01); pal[0] = pack2(l00, l01);
                pah[1] = pack2(h10, h11); pal[1] = pack2(l10, l11);
                split_bf16(s[2*kk+1][0], h00, l00);
                split_bf16(s[2*kk+1][1], h01, l01);
                split_bf16(s[2*kk+1][2], h10, l10);
                split_bf16(s[2*kk+1][3], h11, l11);
                pah[2] = pack2(h00, h01); pal[2] = pack2(l00, l01);
                pah[3] = pack2(h10, h11); pal[3] = pack2(l10, l11);
            }
            const int pa = kk * 8 + tig;
            #pragma unroll
            for (int ni = 0; ni < 8; ni++) {
                unsigned vh[2], vl[2];
                vh[0] = sVh[(ni * 8 + g) * AP + pa];
                vh[1] = sVh[(ni * 8 + g) * AP + pa + 4];
                vl[0] = sVl[(ni * 8 + g) * AP + pa];
                vl[1] = sVl[(ni * 8 + g) * AP + pa + 4];
                mma16816(o[ni], pah, vh);
                mma16816(o[ni], pah, vl);
                mma16816(o[ni], pal, vh);
            }
        }
        __syncthreads();
    }

    // finalize: z = O / l, split to hi/lo bf16, write g_Ah/g_Al directly
    float inv0 = 1.0f / l0, inv1 = 1.0f / l1;
    size_t row0 = rowQ0 + w * 16 + g;
    size_t row1 = row0 + 8;
    #pragma unroll
    for (int ni = 0; ni < 8; ni++) {
        int col = h * DH + ni * 8 + 2 * tig;
        float z00 = o[ni][0] * inv0, z01 = o[ni][1] * inv0;
        float z10 = o[ni][2] * inv1, z11 = o[ni][3] * inv1;
        __nv_bfloat16 hh, ll, hh2, ll2;
        split_bf16(z00, hh, ll);  split_bf16(z01, hh2, ll2);
        *(unsigned*)&g_Ah[row0 * Dn + col] = pack2(hh, hh2);
        *(unsigned*)&g_Al[row0 * Dn + col] = pack2(ll, ll2);
        split_bf16(z10, hh, ll);  split_bf16(z11, hh2, ll2);
        *(unsigned*)&g_Ah[row1 * Dn + col] = pack2(hh, hh2);
        *(unsigned*)&g_Al[row1 * Dn + col] = pack2(ll, ll2);
    }
}

// ---------------------------------------------------------------------------
extern "C" void kernel_launch(void* const* d_in, const int* in_sizes, int n_in,
                              void* d_out, int out_size) {
    const float* x     = (const float*)d_in[0];
    const float* W_qkv = (const float*)d_in[2];
    const float* b_qkv = (const float*)d_in[3];
    const float* W_o   = (const float*)d_in[4];
    const float* b_o   = (const float*)d_in[5];
    const float* wq    = (const float*)d_in[6];
    const float* wk    = (const float*)d_in[7];
    float* out = (float*)d_out;

    void *qkv_ptr, *ah, *al, *wth, *wtl, *woth, *wotl;
    cudaGetSymbolAddress(&qkv_ptr, g_qkv);
    cudaGetSymbolAddress(&ah, g_Ah);
    cudaGetSymbolAddress(&al, g_Al);
    cudaGetSymbolAddress(&wth, g_Wth);
    cudaGetSymbolAddress(&wtl, g_Wtl);
    cudaGetSymbolAddress(&woth, g_Woth);
    cudaGetSymbolAddress(&wotl, g_Wotl);

    const int gemm_smem = 2 * STAGE_U32 * 4;   // 81920 B
    cudaFuncSetAttribute(gemm_bf16x3_db,
                         cudaFuncAttributeMaxDynamicSharedMemorySize, gemm_smem);
    const int attn_smem = 6 * ATILE * 4;       // 55296 B
    cudaFuncSetAttribute(attn_mma_kernel,
                         cudaFuncAttributeMaxDynamicSharedMemorySize, attn_smem);

    // 0) Preprocessing: split x; transpose+split weights
    split_kernel<<<1024, 256>>>(x, (__nv_bfloat16*)ah, (__nv_bfloat16*)al,
                                (size_t)Mrows * Dn / 4);
    {
        dim3 grid(N3 / 32, Dn / 32);
        tsplit_kernel<<<grid, dim3(32, 8)>>>(W_qkv, (__nv_bfloat16*)wth,
                                             (__nv_bfloat16*)wtl, Dn, N3);
    }
    {
        dim3 grid(Dn / 32, Dn / 32);
        tsplit_kernel<<<grid, dim3(32, 8)>>>(W_o, (__nv_bfloat16*)woth,
                                             (__nv_bfloat16*)wotl, Dn, Dn);
    }

    // 1) QKV GEMM
    {
        dim3 grid(N3 / 128, Mrows / 128);
        gemm_bf16x3_db<<<grid, 256, gemm_smem>>>(
            (const __nv_bfloat16*)ah, (const __nv_bfloat16*)al,
            (const __nv_bfloat16*)wth, (const __nv_bfloat16*)wtl,
            b_qkv, (float*)qkv_ptr, N3, Dn);
    }

    // 2) RMSNorm + split q,k; transpose-split v
    {
        int total_warps = Mrows * NH * 2;
        int blocks = (total_warps * 32) / 256;
        rmsnorm_split_kernel<<<blocks, 256>>>(wq, wk);
    }
    {
        dim3 grid(Sn / 64, NH, Bn);
        vsplit_kernel<<<grid, 256>>>();
    }

    // 3) Flash attention (bf16x3 mma.sync) — writes split output to g_Ah/g_Al
    {
        dim3 grid(Sn / 64, NH, Bn);
        attn_mma_kernel<<<grid, 128, attn_smem>>>();
    }

    // 4) Output projection
    {
        dim3 grid(Dn / 128, Mrows / 128);
        gemm_bf16x3_db<<<grid, 256, gemm_smem>>>(
            (const __nv_bfloat16*)ah, (const __nv_bfloat16*)al,
            (const __nv_bfloat16*)woth, (const __nv_bfloat16*)wotl,
            b_o, out, Dn, Dn);
    }
}

// round 8
// speedup vs baseline: 3.4847x; 1.0461x over previous
#include <cuda_runtime.h>
#include <cuda_bf16.h>
#include <math.h>
#include <stdint.h>

#define Bn 4
#define Sn 2048
#define Dn 1024
#define NH 16
#define DH 64
#define Mrows (Bn*Sn)      // 8192
#define N3 (3*Dn)          // 3072

// Scratch (device globals: allocation-free per harness rules)
__device__ float g_qkv[(size_t)Mrows * N3];            // 96 MB
__device__ __nv_bfloat16 g_Ah[(size_t)Mrows * Dn];     // x split hi / attn-out hi
__device__ __nv_bfloat16 g_Al[(size_t)Mrows * Dn];
__device__ __nv_bfloat16 g_Wth[(size_t)N3 * Dn];       // W_qkv^T hi [N][K]
__device__ __nv_bfloat16 g_Wtl[(size_t)N3 * Dn];
__device__ __nv_bfloat16 g_Woth[(size_t)Dn * Dn];      // W_o^T hi
__device__ __nv_bfloat16 g_Wotl[(size_t)Dn * Dn];
__device__ __nv_bfloat16 g_Qh[(size_t)Mrows * Dn];     // rmsnormed q split
__device__ __nv_bfloat16 g_Ql[(size_t)Mrows * Dn];
__device__ __nv_bfloat16 g_Kh[(size_t)Mrows * Dn];     // rmsnormed k split
__device__ __nv_bfloat16 g_Kl[(size_t)Mrows * Dn];
__device__ __nv_bfloat16 g_Vth[(size_t)Mrows * Dn];    // V^T split: [(b*NH+h)*DH+d][s]
__device__ __nv_bfloat16 g_Vtl[(size_t)Mrows * Dn];

__device__ __forceinline__ void split_bf16(float x, __nv_bfloat16& h, __nv_bfloat16& l) {
    h = __float2bfloat16_rn(x);
    l = __float2bfloat16_rn(x - __bfloat162float(h));
}
__device__ __forceinline__ unsigned pack2(__nv_bfloat16 lo, __nv_bfloat16 hi) {
    __nv_bfloat162 p(lo, hi);
    return *(unsigned*)&p;
}
__device__ __forceinline__ void mma16816(float* c, const unsigned* a, const unsigned* b) {
    asm volatile(
        "mma.sync.aligned.m16n8k16.row.col.f32.bf16.bf16.f32 "
        "{%0,%1,%2,%3}, {%4,%5,%6,%7}, {%8,%9}, {%0,%1,%2,%3};"
        : "+f"(c[0]), "+f"(c[1]), "+f"(c[2]), "+f"(c[3])
        : "r"(a[0]), "r"(a[1]), "r"(a[2]), "r"(a[3]), "r"(b[0]), "r"(b[1]));
}
__device__ __forceinline__ void cp16(unsigned smem_addr, const void* gptr) {
    asm volatile("cp.async.cg.shared.global [%0], [%1], 16;"
                 :: "r"(smem_addr), "l"(gptr));
}
__device__ __forceinline__ void ldsm4(unsigned& r0, unsigned& r1,
                                      unsigned& r2, unsigned& r3, unsigned addr) {
    asm volatile("ldmatrix.sync.aligned.m8n8.x4.shared.b16 {%0,%1,%2,%3}, [%4];"
                 : "=r"(r0), "=r"(r1), "=r"(r2), "=r"(r3) : "r"(addr));
}

// ---------------------------------------------------------------------------
// Elementwise split: fp32 -> (hi, lo) bf16
// ---------------------------------------------------------------------------
__global__ void split_kernel(const float* __restrict__ in,
                             __nv_bfloat16* __restrict__ h,
                             __nv_bfloat16* __restrict__ l, size_t n4) {
    size_t i = (size_t)blockIdx.x * blockDim.x + threadIdx.x;
    size_t stride = (size_t)gridDim.x * blockDim.x;
    for (; i < n4; i += stride) {
        float4 v = ((const float4*)in)[i];
        __nv_bfloat16 h0,l0,h1,l1,h2,l2,h3,l3;
        split_bf16(v.x, h0, l0); split_bf16(v.y, h1, l1);
        split_bf16(v.z, h2, l2); split_bf16(v.w, h3, l3);
        __nv_bfloat162 hh0(h0, h1), hh1(h2, h3), ll0(l0, l1), ll1(l2, l3);
        ((__nv_bfloat162*)h)[i * 2]     = hh0;
        ((__nv_bfloat162*)h)[i * 2 + 1] = hh1;
        ((__nv_bfloat162*)l)[i * 2]     = ll0;
        ((__nv_bfloat162*)l)[i * 2 + 1] = ll1;
    }
}

// ---------------------------------------------------------------------------
// Transpose + split: W[K][N] fp32 -> Wt hi/lo [N][K] bf16
// ---------------------------------------------------------------------------
__global__ void tsplit_kernel(const float* __restrict__ W,
                              __nv_bfloat16* __restrict__ th,
                              __nv_bfloat16* __restrict__ tl, int K, int N) {
    __shared__ float t[32][33];
    int n0 = blockIdx.x * 32, k0 = blockIdx.y * 32;
    int tx = threadIdx.x, ty = threadIdx.y;           // (32, 8)
    #pragma unroll
    for (int i = ty; i < 32; i += 8)
        t[i][tx] = W[(size_t)(k0 + i) * N + n0 + tx];
    __syncthreads();
    #pragma unroll
    for (int i = ty; i < 32; i += 8) {
        float v = t[tx][i];
        __nv_bfloat16 h, l;
        split_bf16(v, h, l);
        th[(size_t)(n0 + i) * K + k0 + tx] = h;
        tl[(size_t)(n0 + i) * K + k0 + tx] = l;
    }
}

// ---------------------------------------------------------------------------
// bf16x3 double-buffered cp.async GEMM, BK=32 / pitch-20, 2 CTAs/SM,
// ldmatrix fragment loads.
// ---------------------------------------------------------------------------
#define BKK 32
#define PITCH 20                       // 16 data u32 + 4 pad (5x16B, coprime 8)
#define TILE_U32 (128 * PITCH)
#define TILEB (TILE_U32 * 4)
#define STAGE_U32 (4 * TILE_U32)

__global__ __launch_bounds__(256, 2)
void gemm_bf16x3_db(const __nv_bfloat16* __restrict__ Ah,
                    const __nv_bfloat16* __restrict__ Al,
                    const __nv_bfloat16* __restrict__ Bth,
                    const __nv_bfloat16* __restrict__ Btl,
                    const float* __restrict__ bias,
                    float* __restrict__ C, int Nz, int Kz) {
    extern __shared__ unsigned sm[];

    const int tid  = threadIdx.x;
    const int lane = tid & 31;
    const int wid  = tid >> 5;
    const int wm   = wid >> 2;
    const int wn   = wid & 3;
    const int g    = lane >> 2;
    const int tig  = lane & 3;
    const int lane8 = lane & 7;
    const int lb3  = (lane >> 3) & 1;
    const int lb4  = (lane >> 4) & 1;

    const int rowBase = blockIdx.y * 128;
    const int colBase = blockIdx.x * 128;

    const int r0 = tid >> 2;           // cp.async row, +64 for it2=1
    const int c4 = tid & 3;            // 16B sector in row

    const unsigned smem_base = (unsigned)__cvta_generic_to_shared(sm);

    // ldmatrix per-lane address offsets (byte units, row pitch 80B)
    const unsigned a_off = (unsigned)((wm * 64 + lane8 + lb3 * 8) * 80 + lb4 * 16);
    const unsigned b_off = (unsigned)((wn * 32 + lane8 + lb4 * 8) * 80 + lb3 * 16);

    float acc[4][4][4];
    #pragma unroll
    for (int i = 0; i < 4; i++)
        #pragma unroll
        for (int j = 0; j < 4; j++)
            #pragma unroll
            for (int q = 0; q < 4; q++) acc[i][j][q] = 0.0f;

    const int NIT = Kz / BKK;

    auto load_stage = [&](int it, int buf) {
        const int k0 = it * BKK;
        const unsigned sbase = smem_base + buf * STAGE_U32 * 4;
        #pragma unroll
        for (int it2 = 0; it2 < 2; it2++) {
            int row = r0 + it2 * 64;
            unsigned soff = (unsigned)(row * PITCH + c4 * 4) * 4;
            const __nv_bfloat16* gA   = Ah  + (size_t)(rowBase + row) * Kz + k0 + c4 * 8;
            const __nv_bfloat16* gAl2 = Al  + (size_t)(rowBase + row) * Kz + k0 + c4 * 8;
            const __nv_bfloat16* gB   = Bth + (size_t)(colBase + row) * Kz + k0 + c4 * 8;
            const __nv_bfloat16* gBl2 = Btl + (size_t)(colBase + row) * Kz + k0 + c4 * 8;
            cp16(sbase + soff, gA);
            cp16(sbase + TILEB + soff, gAl2);
            cp16(sbase + 2 * TILEB + soff, gB);
            cp16(sbase + 3 * TILEB + soff, gBl2);
        }
        asm volatile("cp.async.commit_group;");
    };

    load_stage(0, 0);

    for (int it = 0; it < NIT; it++) {
        const int buf = it & 1;
        if (it + 1 < NIT) {
            load_stage(it + 1, (it + 1) & 1);
            asm volatile("cp.async.wait_group 1;");
        } else {
            asm volatile("cp.async.wait_group 0;");
        }
        __syncthreads();

        const unsigned stg = smem_base + buf * STAGE_U32 * 4;

        #pragma unroll
        for (int kk8 = 0; kk8 < 2; kk8++) {
            unsigned ahi[4][4], alo[4][4], bhi[4][2], blo[4][2];
            #pragma unroll
            for (int mi = 0; mi < 4; mi++) {
                unsigned ad = stg + a_off + (unsigned)(mi * 16 * 80 + kk8 * 32);
                ldsm4(ahi[mi][0], ahi[mi][1], ahi[mi][2], ahi[mi][3], ad);
                ldsm4(alo[mi][0], alo[mi][1], alo[mi][2], alo[mi][3], ad + TILEB);
            }
            #pragma unroll
            for (int p = 0; p < 2; p++) {
                unsigned bd = stg + 2 * TILEB + b_off + (unsigned)(p * 16 * 80 + kk8 * 32);
                ldsm4(bhi[2*p][0], bhi[2*p][1], bhi[2*p+1][0], bhi[2*p+1][1], bd);
                ldsm4(blo[2*p][0], blo[2*p][1], blo[2*p+1][0], blo[2*p+1][1], bd + TILEB);
            }
            #pragma unroll
            for (int mi = 0; mi < 4; mi++)
                #pragma unroll
                for (int ni = 0; ni < 4; ni++) {
                    mma16816(acc[mi][ni], ahi[mi], bhi[ni]);
                    mma16816(acc[mi][ni], ahi[mi], blo[ni]);
                    mma16816(acc[mi][ni], alo[mi], bhi[ni]);
                }
        }
        __syncthreads();
    }

    #pragma unroll
    for (int mi = 0; mi < 4; mi++) {
        int row0 = rowBase + wm * 64 + mi * 16 + g;
        int row1 = row0 + 8;
        #pragma unroll
        for (int ni = 0; ni < 4; ni++) {
            int col = colBase + wn * 32 + ni * 8 + tig * 2;
            float b0 = __ldg(&bias[col]);
            float b1 = __ldg(&bias[col + 1]);
            C[(size_t)row0 * Nz + col]     = acc[mi][ni][0] + b0;
            C[(size_t)row0 * Nz + col + 1] = acc[mi][ni][1] + b1;
            C[(size_t)row1 * Nz + col]     = acc[mi][ni][2] + b0;
            C[(size_t)row1 * Nz + col + 1] = acc[mi][ni][3] + b1;
        }
    }
}

// ---------------------------------------------------------------------------
// Fused RMSNorm + bf16 hi/lo split: g_qkv q/k sections -> g_Qh/Ql/Kh/Kl.
// ---------------------------------------------------------------------------
__global__ void rmsnorm_split_kernel(const float* __restrict__ wq,
                                     const float* __restrict__ wk) {
    int gw = (blockIdx.x * blockDim.x + threadIdx.x) >> 5;
    int lane = threadIdx.x & 31;
    int which = gw & 1;
    int head = (gw >> 1) & 15;
    int row = gw >> 5;
    if (row >= Mrows) return;

    const float* p = g_qkv + (size_t)row * N3 + which * Dn + head * DH;
    float2 v = ((const float2*)p)[lane];
    float ss = v.x * v.x + v.y * v.y;
    #pragma unroll
    for (int o = 16; o; o >>= 1) ss += __shfl_xor_sync(0xffffffffu, ss, o);
    float inv = rsqrtf(ss * (1.0f / DH) + 1e-6f);
    const float* w = which ? wk : wq;
    float2 wv = ((const float2*)w)[lane];
    float a0 = v.x * inv * wv.x;
    float a1 = v.y * inv * wv.y;

    __nv_bfloat16 h0, l0, h1, l1;
    split_bf16(a0, h0, l0);
    split_bf16(a1, h1, l1);
    size_t off = (size_t)row * Dn + head * DH;
    __nv_bfloat16* dh = (which ? g_Kh : g_Qh) + off;
    __nv_bfloat16* dl = (which ? g_Kl : g_Ql) + off;
    ((__nv_bfloat162*)dh)[lane] = __nv_bfloat162(h0, h1);
    ((__nv_bfloat162*)dl)[lane] = __nv_bfloat162(l0, l1);
}

// ---------------------------------------------------------------------------
// V transpose + split: g_qkv v section [b,s][h,d] -> g_Vth/Vtl [(b,h,d)][s]
// ---------------------------------------------------------------------------
__global__ void vsplit_kernel() {
    __shared__ float t[64][65];
    int s0 = blockIdx.x * 64;
    int h = blockIdx.y, b = blockIdx.z;
    int tid = threadIdx.x;
    #pragma unroll
    for (int it = 0; it < 16; it++) {
        int idx = tid + it * 256;
        int sr = idx >> 6, d = idx & 63;
        t[sr][d] = g_qkv[((size_t)b * Sn + s0 + sr) * N3 + 2 * Dn + h * DH + d];
    }
    __syncthreads();
    #pragma unroll
    for (int it = 0; it < 16; it++) {
        int idx = tid + it * 256;
        int d = idx >> 6, sc = idx & 63;
        float v = t[sc][d];
        __nv_bfloat16 hh, ll;
        split_bf16(v, hh, ll);
        size_t off = ((size_t)(b * NH + h) * DH + d) * Sn + s0 + sc;
        g_Vth[off] = hh;
        g_Vtl[off] = ll;
    }
}

// ---------------------------------------------------------------------------
// Flash attention with bf16x3 mma.sync + ldmatrix fragment loads.
// Smem pitch 36 u32 = 144B = 9x16B chunks (coprime 8 -> LDSM conflict-free).
// ---------------------------------------------------------------------------
#define AP 36
#define ATILE (64 * AP)
#define ATB (ATILE * 4)                // tile bytes 9216

__global__ __launch_bounds__(128) void attn_mma_kernel() {
    extern __shared__ unsigned smu[];

    const int tid  = threadIdx.x;
    const int lane = tid & 31;
    const int w    = tid >> 5;
    const int g    = lane >> 2;
    const int tig  = lane & 3;
    const int lane8 = lane & 7;
    const int lb3  = (lane >> 3) & 1;
    const int lb4  = (lane >> 4) & 1;

    const int qt = gridDim.x - 1 - blockIdx.x;
    const int h  = blockIdx.y;
    const int b  = blockIdx.z;

    const size_t rowQ0 = (size_t)b * Sn + qt * 64;
    const size_t qk_off = h * DH;
    const size_t v_row0 = (size_t)(b * NH + h) * DH;

    const unsigned smu_b = (unsigned)__cvta_generic_to_shared(smu);
    // tiles: Qh=0, Ql=1, Kh=2, Kl=3, Vh=4, Vl=5 (x ATB bytes)
    const int m0r = w * 16;
    const unsigned q_loff = (unsigned)((m0r + lane8 + lb3 * 8) * 144 + lb4 * 16);
    const unsigned n_loff = (unsigned)((lane8 + lb4 * 8) * 144 + lb3 * 16);

    #pragma unroll
    for (int it = 0; it < 4; it++) {
        int idx = tid + it * 128;
        int r = idx >> 3, q4 = idx & 7;
        const uint4* gh = (const uint4*)(g_Qh + (rowQ0 + r) * Dn + qk_off);
        const uint4* gl = (const uint4*)(g_Ql + (rowQ0 + r) * Dn + qk_off);
        ((uint4*)(smu + r * AP))[q4] = gh[q4];
        ((uint4*)(smu + ATILE + r * AP))[q4] = gl[q4];
    }

    float o[8][4];
    #pragma unroll
    for (int ni = 0; ni < 8; ni++)
        #pragma unroll
        for (int c = 0; c < 4; c++) o[ni][c] = 0.0f;
    float m0 = -INFINITY, m1 = -INFINITY, l0 = 0.0f, l1 = 0.0f;

    __syncthreads();

    for (int kt = 0; kt <= qt; kt++) {
        const size_t rowK0 = (size_t)b * Sn + kt * 64;
        #pragma unroll
        for (int it = 0; it < 4; it++) {
            int idx = tid + it * 128;
            int r = idx >> 3, q4 = idx & 7;
            const uint4* kh = (const uint4*)(g_Kh + (rowK0 + r) * Dn + qk_off);
            const uint4* kl = (const uint4*)(g_Kl + (rowK0 + r) * Dn + qk_off);
            ((uint4*)(smu + 2 * ATILE + r * AP))[q4] = kh[q4];
            ((uint4*)(smu + 3 * ATILE + r * AP))[q4] = kl[q4];
            const uint4* vh = (const uint4*)(g_Vth + (v_row0 + r) * Sn + kt * 64);
            const uint4* vl = (const uint4*)(g_Vtl + (v_row0 + r) * Sn + kt * 64);
            ((uint4*)(smu + 4 * ATILE + r * AP))[q4] = vh[q4];
            ((uint4*)(smu + 5 * ATILE + r * AP))[q4] = vl[q4];
        }
        __syncthreads();

        float s[8][4];
        #pragma unroll
        for (int ni = 0; ni < 8; ni++)
            #pragma unroll
            for (int c = 0; c < 4; c++) s[ni][c] = 0.0f;

        #pragma unroll
        for (int kk = 0; kk < 4; kk++) {
            unsigned ah[4], al[4];
            ldsm4(ah[0], ah[1], ah[2], ah[3], smu_b + q_loff + kk * 32);
            ldsm4(al[0], al[1], al[2], al[3], smu_b + ATB + q_loff + kk * 32);
            #pragma unroll
            for (int p = 0; p < 4; p++) {
                unsigned bh[4], bl[4];
                unsigned kd = smu_b + 2 * ATB + n_loff + (unsigned)(p * 16 * 144 + kk * 32);
                ldsm4(bh[0], bh[1], bh[2], bh[3], kd);
                ldsm4(bl[0], bl[1], bl[2], bl[3], kd + ATB);
                mma16816(s[2*p],   ah, bh);
                mma16816(s[2*p],   ah, bl);
                mma16816(s[2*p],   al, bh);
                mma16816(s[2*p+1], ah, bh + 2);
                mma16816(s[2*p+1], ah, bl + 2);
                mma16816(s[2*p+1], al, bh + 2);
            }
        }

        if (kt == qt) {
            #pragma unroll
            for (int ni = 0; ni < 8; ni++) {
                int col = ni * 8 + 2 * tig;
                int r0 = m0r + g, r1 = r0 + 8;
                if (col > r0)     s[ni][0] = -INFINITY;
                if (col + 1 > r0) s[ni][1] = -INFINITY;
                if (col > r1)     s[ni][2] = -INFINITY;
                if (col + 1 > r1) s[ni][3] = -INFINITY;
            }
        }

        float rm0 = -INFINITY, rm1 = -INFINITY;
        #pragma unroll
        for (int ni = 0; ni < 8; ni++) {
            rm0 = fmaxf(rm0, fmaxf(s[ni][0], s[ni][1]));
            rm1 = fmaxf(rm1, fmaxf(s[ni][2], s[ni][3]));
        }
        rm0 = fmaxf(rm0, __shfl_xor_sync(0xffffffffu, rm0, 1));
        rm0 = fmaxf(rm0, __shfl_xor_sync(0xffffffffu, rm0, 2));
        rm1 = fmaxf(rm1, __shfl_xor_sync(0xffffffffu, rm1, 1));
        rm1 = fmaxf(rm1, __shfl_xor_sync(0xffffffffu, rm1, 2));
        float mn0 = fmaxf(m0, rm0), mn1 = fmaxf(m1, rm1);

        float rs0 = 0.0f, rs1 = 0.0f;
        #pragma unroll
        for (int ni = 0; ni < 8; ni++) {
            s[ni][0] = __expf(s[ni][0] - mn0);
            s[ni][1] = __expf(s[ni][1] - mn0);
            s[ni][2] = __expf(s[ni][2] - mn1);
            s[ni][3] = __expf(s[ni][3] - mn1);
            rs0 += s[ni][0] + s[ni][1];
            rs1 += s[ni][2] + s[ni][3];
        }
        rs0 += __shfl_xor_sync(0xffffffffu, rs0, 1);
        rs0 += __shfl_xor_sync(0xffffffffu, rs0, 2);
        rs1 += __shfl_xor_sync(0xffffffffu, rs1, 1);
        rs1 += __shfl_xor_sync(0xffffffffu, rs1, 2);

        float al0 = __expf(m0 - mn0), al1 = __expf(m1 - mn1);
        l0 = l0 * al0 + rs0;
        l1 = l1 * al1 + rs1;
        m0 = mn0; m1 = mn1;
        #pragma unroll
        for (int ni = 0; ni < 8; ni++) {
            o[ni][0] *= al0; o[ni][1] *= al0;
            o[ni][2] *= al1; o[ni][3] *= al1;
        }

        #pragma unroll
        for (int kk = 0; kk < 4; kk++) {
            unsigned pah[4], pal[4];
            {
                __nv_bfloat16 h00,l00,h01,l01,h10,l10,h11,l11;
                split_bf16(s[2*kk][0], h00, l00);
                split_bf16(s[2*kk][1], h01, l01);
                split_bf16(s[2*kk][2], h10, l10);
                split_bf16(s[2*kk][3], h11, l11);
                pah[0] = pack2(h00, h01); pal[0] = pack2(l00, l01);
                pah[1] = pack2(h10, h11); pal[1] = pack2(l10, l11);
                split_bf16(s[2*kk+1][0], h00, l00);
                split_bf16(s[2*kk+1][1], h01, l01);
                split_bf16(s[2*kk+1][2], h10, l10);
                split_bf16(s[2*kk+1][3], h11, l11);
                pah[2] = pack2(h00, h01); pal[2] = pack2(l00, l01);
                pah[3] = pack2(h10, h11); pal[3] = pack2(l10, l11);
            }
            #pragma unroll
            for (int p = 0; p < 4; p++) {
                unsigned vh[4], vl[4];
                unsigned vd = smu_b + 4 * ATB + n_loff + (unsigned)(p * 16 * 144 + kk * 32);
                ldsm4(vh[0], vh[1], vh[2], vh[3], vd);
                ldsm4(vl[0], vl[1], vl[2], vl[3], vd + ATB);
                mma16816(o[2*p],   pah, vh);
                mma16816(o[2*p],   pah, vl);
                mma16816(o[2*p],   pal, vh);
                mma16816(o[2*p+1], pah, vh + 2);
                mma16816(o[2*p+1], pah, vl + 2);
                mma16816(o[2*p+1], pal, vh + 2);
            }
        }
        __syncthreads();
    }

    // finalize: z = O / l, split to hi/lo bf16, write g_Ah/g_Al directly
    float inv0 = 1.0f / l0, inv1 = 1.0f / l1;
    size_t row0 = rowQ0 + w * 16 + g;
    size_t row1 = row0 + 8;
    #pragma unroll
    for (int ni = 0; ni < 8; ni++) {
        int col = h * DH + ni * 8 + 2 * tig;
        float z00 = o[ni][0] * inv0, z01 = o[ni][1] * inv0;
        float z10 = o[ni][2] * inv1, z11 = o[ni][3] * inv1;
        __nv_bfloat16 hh, ll, hh2, ll2;
        split_bf16(z00, hh, ll);  split_bf16(z01, hh2, ll2);
        *(unsigned*)&g_Ah[row0 * Dn + col] = pack2(hh, hh2);
        *(unsigned*)&g_Al[row0 * Dn + col] = pack2(ll, ll2);
        split_bf16(z10, hh, ll);  split_bf16(z11, hh2, ll2);
        *(unsigned*)&g_Ah[row1 * Dn + col] = pack2(hh, hh2);
        *(unsigned*)&g_Al[row1 * Dn + col] = pack2(ll, ll2);
    }
}

// ---------------------------------------------------------------------------
extern "C" void kernel_launch(void* const* d_in, const int* in_sizes, int n_in,
                              void* d_out, int out_size) {
    const float* x     = (const float*)d_in[0];
    const float* W_qkv = (const float*)d_in[2];
    const float* b_qkv = (const float*)d_in[3];
    const float* W_o   = (const float*)d_in[4];
    const float* b_o   = (const float*)d_in[5];
    const float* wq    = (const float*)d_in[6];
    const float* wk    = (const float*)d_in[7];
    float* out = (float*)d_out;

    void *qkv_ptr, *ah, *al, *wth, *wtl, *woth, *wotl;
    cudaGetSymbolAddress(&qkv_ptr, g_qkv);
    cudaGetSymbolAddress(&ah, g_Ah);
    cudaGetSymbolAddress(&al, g_Al);
    cudaGetSymbolAddress(&wth, g_Wth);
    cudaGetSymbolAddress(&wtl, g_Wtl);
    cudaGetSymbolAddress(&woth, g_Woth);
    cudaGetSymbolAddress(&wotl, g_Wotl);

    const int gemm_smem = 2 * STAGE_U32 * 4;   // 81920 B
    cudaFuncSetAttribute(gemm_bf16x3_db,
                         cudaFuncAttributeMaxDynamicSharedMemorySize, gemm_smem);
    const int attn_smem = 6 * ATILE * 4;       // 55296 B
    cudaFuncSetAttribute(attn_mma_kernel,
                         cudaFuncAttributeMaxDynamicSharedMemorySize, attn_smem);

    // 0) Preprocessing: split x; transpose+split weights
    split_kernel<<<1024, 256>>>(x, (__nv_bfloat16*)ah, (__nv_bfloat16*)al,
                                (size_t)Mrows * Dn / 4);
    {
        dim3 grid(N3 / 32, Dn / 32);
        tsplit_kernel<<<grid, dim3(32, 8)>>>(W_qkv, (__nv_bfloat16*)wth,
                                             (__nv_bfloat16*)wtl, Dn, N3);
    }
    {
        dim3 grid(Dn / 32, Dn / 32);
        tsplit_kernel<<<grid, dim3(32, 8)>>>(W_o, (__nv_bfloat16*)woth,
                                             (__nv_bfloat16*)wotl, Dn, Dn);
    }

    // 1) QKV GEMM
    {
        dim3 grid(N3 / 128, Mrows / 128);
        gemm_bf16x3_db<<<grid, 256, gemm_smem>>>(
            (const __nv_bfloat16*)ah, (const __nv_bfloat16*)al,
            (const __nv_bfloat16*)wth, (const __nv_bfloat16*)wtl,
            b_qkv, (float*)qkv_ptr, N3, Dn);
    }

    // 2) RMSNorm + split q,k; transpose-split v
    {
        int total_warps = Mrows * NH * 2;
        int blocks = (total_warps * 32) / 256;
        rmsnorm_split_kernel<<<blocks, 256>>>(wq, wk);
    }
    {
        dim3 grid(Sn / 64, NH, Bn);
        vsplit_kernel<<<grid, 256>>>();
    }

    // 3) Flash attention (bf16x3 mma.sync + ldmatrix)
    {
        dim3 grid(Sn / 64, NH, Bn);
        attn_mma_kernel<<<grid, 128, attn_smem>>>();
    }

    // 4) Output projection
    {
        dim3 grid(Dn / 128, Mrows / 128);
        gemm_bf16x3_db<<<grid, 256, gemm_smem>>>(
            (const __nv_bfloat16*)ah, (const __nv_bfloat16*)al,
            (const __nv_bfloat16*)woth, (const __nv_bfloat16*)wotl,
            b_o, out, Dn, Dn);
    }
}

// round 9
// speedup vs baseline: 4.2860x; 1.2300x over previous
#include <cuda_runtime.h>
#include <cuda_bf16.h>
#include <cuda_fp16.h>
#include <math.h>
#include <stdint.h>

#define Bn 4
#define Sn 2048
#define Dn 1024
#define NH 16
#define DH 64
#define Mrows (Bn*Sn)      // 8192
#define N3 (3*Dn)          // 3072

// Scratch (device globals: allocation-free per harness rules)
__device__ float g_qkv[(size_t)Mrows * N3];            // 96 MB
__device__ __half g_Ah[(size_t)Mrows * Dn];            // fp16(x) / fp16(attn out)
__device__ __half g_Wth[(size_t)N3 * Dn];              // W_qkv^T hi [N][K]
__device__ __half g_Wtl[(size_t)N3 * Dn];              // W_qkv^T lo
__device__ __half g_Woth[(size_t)Dn * Dn];             // W_o^T hi
__device__ __half g_Wotl[(size_t)Dn * Dn];
__device__ __nv_bfloat16 g_Qh[(size_t)Mrows * Dn];     // rmsnormed q split (bf16)
__device__ __nv_bfloat16 g_Ql[(size_t)Mrows * Dn];
__device__ __nv_bfloat16 g_Kh[(size_t)Mrows * Dn];
__device__ __nv_bfloat16 g_Kl[(size_t)Mrows * Dn];
__device__ __nv_bfloat16 g_Vth[(size_t)Mrows * Dn];    // V^T split: [(b*NH+h)*DH+d][s]
__device__ __nv_bfloat16 g_Vtl[(size_t)Mrows * Dn];

__device__ __forceinline__ void split_bf16(float x, __nv_bfloat16& h, __nv_bfloat16& l) {
    h = __float2bfloat16_rn(x);
    l = __float2bfloat16_rn(x - __bfloat162float(h));
}
__device__ __forceinline__ unsigned pack2(__nv_bfloat16 lo, __nv_bfloat16 hi) {
    __nv_bfloat162 p(lo, hi);
    return *(unsigned*)&p;
}
__device__ __forceinline__ void mma16816(float* c, const unsigned* a, const unsigned* b) {
    asm volatile(
        "mma.sync.aligned.m16n8k16.row.col.f32.bf16.bf16.f32 "
        "{%0,%1,%2,%3}, {%4,%5,%6,%7}, {%8,%9}, {%0,%1,%2,%3};"
        : "+f"(c[0]), "+f"(c[1]), "+f"(c[2]), "+f"(c[3])
        : "r"(a[0]), "r"(a[1]), "r"(a[2]), "r"(a[3]), "r"(b[0]), "r"(b[1]));
}
__device__ __forceinline__ void mma16816h(float* c, const unsigned* a, const unsigned* b) {
    asm volatile(
        "mma.sync.aligned.m16n8k16.row.col.f32.f16.f16.f32 "
        "{%0,%1,%2,%3}, {%4,%5,%6,%7}, {%8,%9}, {%0,%1,%2,%3};"
        : "+f"(c[0]), "+f"(c[1]), "+f"(c[2]), "+f"(c[3])
        : "r"(a[0]), "r"(a[1]), "r"(a[2]), "r"(a[3]), "r"(b[0]), "r"(b[1]));
}
__device__ __forceinline__ void cp16(unsigned smem_addr, const void* gptr) {
    asm volatile("cp.async.cg.shared.global [%0], [%1], 16;"
                 :: "r"(smem_addr), "l"(gptr));
}
__device__ __forceinline__ void ldsm4(unsigned& r0, unsigned& r1,
                                      unsigned& r2, unsigned& r3, unsigned addr) {
    asm volatile("ldmatrix.sync.aligned.m8n8.x4.shared.b16 {%0,%1,%2,%3}, [%4];"
                 : "=r"(r0), "=r"(r1), "=r"(r2), "=r"(r3) : "r"(addr));
}

// ---------------------------------------------------------------------------
// fp32 -> fp16 convert (for x)
// ---------------------------------------------------------------------------
__global__ void cvt_f16_kernel(const float* __restrict__ in,
                               __half* __restrict__ out, size_t n4) {
    size_t i = (size_t)blockIdx.x * blockDim.x + threadIdx.x;
    size_t stride = (size_t)gridDim.x * blockDim.x;
    for (; i < n4; i += stride) {
        float4 v = ((const float4*)in)[i];
        __half2 a(__float2half_rn(v.x), __float2half_rn(v.y));
        __half2 b(__float2half_rn(v.z), __float2half_rn(v.w));
        ((__half2*)out)[i * 2]     = a;
        ((__half2*)out)[i * 2 + 1] = b;
    }
}

// ---------------------------------------------------------------------------
// Transpose + fp16 hi/lo split: W[K][N] fp32 -> Wt hi/lo [N][K] fp16
// ---------------------------------------------------------------------------
__global__ void tsplit_f16_kernel(const float* __restrict__ W,
                                  __half* __restrict__ th,
                                  __half* __restrict__ tl, int K, int N) {
    __shared__ float t[32][33];
    int n0 = blockIdx.x * 32, k0 = blockIdx.y * 32;
    int tx = threadIdx.x, ty = threadIdx.y;           // (32, 8)
    #pragma unroll
    for (int i = ty; i < 32; i += 8)
        t[i][tx] = W[(size_t)(k0 + i) * N + n0 + tx];
    __syncthreads();
    #pragma unroll
    for (int i = ty; i < 32; i += 8) {
        float v = t[tx][i];
        __half h = __float2half_rn(v);
        __half l = __float2half_rn(v - __half2float(h));
        th[(size_t)(n0 + i) * K + k0 + tx] = h;
        tl[(size_t)(n0 + i) * K + k0 + tx] = l;
    }
}

// ---------------------------------------------------------------------------
// fp16x2 triple-buffered cp.async GEMM (W-side corrected).
// A: fp16 [M][K]; Bt: hi/lo fp16 [N][K]; C = A@(Bh+Bl) + bias (fp32 out).
// 128x128 blocktile, BK=32, pitch-20 u32, 3 stages x 30KB, 2 CTAs/SM.
// ---------------------------------------------------------------------------
#define BKK 32
#define PITCH 20                       // 16 data u32 + 4 pad (5x16B, coprime 8)
#define TILE_U32 (128 * PITCH)
#define TILEB (TILE_U32 * 4)
#define STAGE_U32 (3 * TILE_U32)       // A, Bh, Bl
#define GEMM_SMEM (3 * STAGE_U32 * 4)  // 3 stages = 92160 B

__global__ __launch_bounds__(256, 2)
void gemm_f16x2(const __half* __restrict__ A,
                const __half* __restrict__ Bth,
                const __half* __restrict__ Btl,
                const float* __restrict__ bias,
                float* __restrict__ C, int Nz, int Kz) {
    extern __shared__ unsigned sm[];

    const int tid  = threadIdx.x;
    const int lane = tid & 31;
    const int wid  = tid >> 5;
    const int wm   = wid >> 2;
    const int wn   = wid & 3;
    const int g    = lane >> 2;
    const int tig  = lane & 3;
    const int lane8 = lane & 7;
    const int lb3  = (lane >> 3) & 1;
    const int lb4  = (lane >> 4) & 1;

    const int rowBase = blockIdx.y * 128;
    const int colBase = blockIdx.x * 128;

    const int r0 = tid >> 2;           // cp.async row, +64 for it2=1
    const int c4 = tid & 3;            // 16B sector in row

    const unsigned smem_base = (unsigned)__cvta_generic_to_shared(sm);

    // ldmatrix per-lane address offsets (byte units, row pitch 80B)
    const unsigned a_off = (unsigned)((wm * 64 + lane8 + lb3 * 8) * 80 + lb4 * 16);
    const unsigned b_off = (unsigned)((wn * 32 + lane8 + lb4 * 8) * 80 + lb3 * 16);

    float acc[4][4][4];
    #pragma unroll
    for (int i = 0; i < 4; i++)
        #pragma unroll
        for (int j = 0; j < 4; j++)
            #pragma unroll
            for (int q = 0; q < 4; q++) acc[i][j][q] = 0.0f;

    const int NIT = Kz / BKK;

    auto load_stage = [&](int it, int buf) {
        const int k0 = it * BKK;
        const unsigned sbase = smem_base + buf * STAGE_U32 * 4;
        #pragma unroll
        for (int it2 = 0; it2 < 2; it2++) {
            int row = r0 + it2 * 64;
            unsigned soff = (unsigned)(row * PITCH + c4 * 4) * 4;
            const __half* gA  = A   + (size_t)(rowBase + row) * Kz + k0 + c4 * 8;
            const __half* gBh = Bth + (size_t)(colBase + row) * Kz + k0 + c4 * 8;
            const __half* gBl = Btl + (size_t)(colBase + row) * Kz + k0 + c4 * 8;
            cp16(sbase + soff, gA);
            cp16(sbase + TILEB + soff, gBh);
            cp16(sbase + 2 * TILEB + soff, gBl);
        }
        asm volatile("cp.async.commit_group;");
    };

    load_stage(0, 0);
    load_stage(1, 1);

    for (int it = 0; it < NIT; it++) {
        const int buf = it % 3;
        if (it + 2 < NIT) {
            load_stage(it + 2, (it + 2) % 3);
            asm volatile("cp.async.wait_group 2;");
        } else if (it + 1 < NIT) {
            asm volatile("cp.async.wait_group 1;");
        } else {
            asm volatile("cp.async.wait_group 0;");
        }
        __syncthreads();

        const unsigned stg = smem_base + buf * STAGE_U32 * 4;

        #pragma unroll
        for (int kk8 = 0; kk8 < 2; kk8++) {
            unsigned a[4][4], bhi[4][2], blo[4][2];
            #pragma unroll
            for (int mi = 0; mi < 4; mi++) {
                unsigned ad = stg + a_off + (unsigned)(mi * 16 * 80 + kk8 * 32);
                ldsm4(a[mi][0], a[mi][1], a[mi][2], a[mi][3], ad);
            }
            #pragma unroll
            for (int p = 0; p < 2; p++) {
                unsigned bd = stg + TILEB + b_off + (unsigned)(p * 16 * 80 + kk8 * 32);
                ldsm4(bhi[2*p][0], bhi[2*p][1], bhi[2*p+1][0], bhi[2*p+1][1], bd);
                ldsm4(blo[2*p][0], blo[2*p][1], blo[2*p+1][0], blo[2*p+1][1], bd + TILEB);
            }
            #pragma unroll
            for (int mi = 0; mi < 4; mi++)
                #pragma unroll
                for (int ni = 0; ni < 4; ni++) {
                    mma16816h(acc[mi][ni], a[mi], bhi[ni]);
                    mma16816h(acc[mi][ni], a[mi], blo[ni]);
                }
        }
        __syncthreads();
    }

    #pragma unroll
    for (int mi = 0; mi < 4; mi++) {
        int row0 = rowBase + wm * 64 + mi * 16 + g;
        int row1 = row0 + 8;
        #pragma unroll
        for (int ni = 0; ni < 4; ni++) {
            int col = colBase + wn * 32 + ni * 8 + tig * 2;
            float b0 = __ldg(&bias[col]);
            float b1 = __ldg(&bias[col + 1]);
            C[(size_t)row0 * Nz + col]     = acc[mi][ni][0] + b0;
            C[(size_t)row0 * Nz + col + 1] = acc[mi][ni][1] + b1;
            C[(size_t)row1 * Nz + col]     = acc[mi][ni][2] + b0;
            C[(size_t)row1 * Nz + col + 1] = acc[mi][ni][3] + b1;
        }
    }
}

// ---------------------------------------------------------------------------
// Fused RMSNorm + bf16 hi/lo split: g_qkv q/k sections -> g_Qh/Ql/Kh/Kl.
// ---------------------------------------------------------------------------
__global__ void rmsnorm_split_kernel(const float* __restrict__ wq,
                                     const float* __restrict__ wk) {
    int gw = (blockIdx.x * blockDim.x + threadIdx.x) >> 5;
    int lane = threadIdx.x & 31;
    int which = gw & 1;
    int head = (gw >> 1) & 15;
    int row = gw >> 5;
    if (row >= Mrows) return;

    const float* p = g_qkv + (size_t)row * N3 + which * Dn + head * DH;
    float2 v = ((const float2*)p)[lane];
    float ss = v.x * v.x + v.y * v.y;
    #pragma unroll
    for (int o = 16; o; o >>= 1) ss += __shfl_xor_sync(0xffffffffu, ss, o);
    float inv = rsqrtf(ss * (1.0f / DH) + 1e-6f);
    const float* w = which ? wk : wq;
    float2 wv = ((const float2*)w)[lane];
    float a0 = v.x * inv * wv.x;
    float a1 = v.y * inv * wv.y;

    __nv_bfloat16 h0, l0, h1, l1;
    split_bf16(a0, h0, l0);
    split_bf16(a1, h1, l1);
    size_t off = (size_t)row * Dn + head * DH;
    __nv_bfloat16* dh = (which ? g_Kh : g_Qh) + off;
    __nv_bfloat16* dl = (which ? g_Kl : g_Ql) + off;
    ((__nv_bfloat162*)dh)[lane] = __nv_bfloat162(h0, h1);
    ((__nv_bfloat162*)dl)[lane] = __nv_bfloat162(l0, l1);
}

// ---------------------------------------------------------------------------
// V transpose + split: g_qkv v section [b,s][h,d] -> g_Vth/Vtl [(b,h,d)][s]
// ---------------------------------------------------------------------------
__global__ void vsplit_kernel() {
    __shared__ float t[64][65];
    int s0 = blockIdx.x * 64;
    int h = blockIdx.y, b = blockIdx.z;
    int tid = threadIdx.x;
    #pragma unroll
    for (int it = 0; it < 16; it++) {
        int idx = tid + it * 256;
        int sr = idx >> 6, d = idx & 63;
        t[sr][d] = g_qkv[((size_t)b * Sn + s0 + sr) * N3 + 2 * Dn + h * DH + d];
    }
    __syncthreads();
    #pragma unroll
    for (int it = 0; it < 16; it++) {
        int idx = tid + it * 256;
        int d = idx >> 6, sc = idx & 63;
        float v = t[sc][d];
        __nv_bfloat16 hh, ll;
        split_bf16(v, hh, ll);
        size_t off = ((size_t)(b * NH + h) * DH + d) * Sn + s0 + sc;
        g_Vth[off] = hh;
        g_Vtl[off] = ll;
    }
}

// ---------------------------------------------------------------------------
// Flash attention with bf16x3 mma.sync + ldmatrix (round-8 verified).
// Epilogue writes z as single fp16 into g_Ah (O-proj input).
// ---------------------------------------------------------------------------
#define AP 36
#define ATILE (64 * AP)
#define ATB (ATILE * 4)                // tile bytes 9216

__global__ __launch_bounds__(128) void attn_mma_kernel() {
    extern __shared__ unsigned smu[];

    const int tid  = threadIdx.x;
    const int lane = tid & 31;
    const int w    = tid >> 5;
    const int g    = lane >> 2;
    const int tig  = lane & 3;
    const int lane8 = lane & 7;
    const int lb3  = (lane >> 3) & 1;
    const int lb4  = (lane >> 4) & 1;

    const int qt = gridDim.x - 1 - blockIdx.x;
    const int h  = blockIdx.y;
    const int b  = blockIdx.z;

    const size_t rowQ0 = (size_t)b * Sn + qt * 64;
    const size_t qk_off = h * DH;
    const size_t v_row0 = (size_t)(b * NH + h) * DH;

    const unsigned smu_b = (unsigned)__cvta_generic_to_shared(smu);
    // tiles: Qh=0, Ql=1, Kh=2, Kl=3, Vh=4, Vl=5 (x ATB bytes)
    const int m0r = w * 16;
    const unsigned q_loff = (unsigned)((m0r + lane8 + lb3 * 8) * 144 + lb4 * 16);
    const unsigned n_loff = (unsigned)((lane8 + lb4 * 8) * 144 + lb3 * 16);

    #pragma unroll
    for (int it = 0; it < 4; it++) {
        int idx = tid + it * 128;
        int r = idx >> 3, q4 = idx & 7;
        const uint4* gh = (const uint4*)(g_Qh + (rowQ0 + r) * Dn + qk_off);
        const uint4* gl = (const uint4*)(g_Ql + (rowQ0 + r) * Dn + qk_off);
        ((uint4*)(smu + r * AP))[q4] = gh[q4];
        ((uint4*)(smu + ATILE + r * AP))[q4] = gl[q4];
    }

    float o[8][4];
    #pragma unroll
    for (int ni = 0; ni < 8; ni++)
        #pragma unroll
        for (int c = 0; c < 4; c++) o[ni][c] = 0.0f;
    float m0 = -INFINITY, m1 = -INFINITY, l0 = 0.0f, l1 = 0.0f;

    __syncthreads();

    for (int kt = 0; kt <= qt; kt++) {
        const size_t rowK0 = (size_t)b * Sn + kt * 64;
        #pragma unroll
        for (int it = 0; it < 4; it++) {
            int idx = tid + it * 128;
            int r = idx >> 3, q4 = idx & 7;
            const uint4* kh = (const uint4*)(g_Kh + (rowK0 + r) * Dn + qk_off);
            const uint4* kl = (const uint4*)(g_Kl + (rowK0 + r) * Dn + qk_off);
            ((uint4*)(smu + 2 * ATILE + r * AP))[q4] = kh[q4];
            ((uint4*)(smu + 3 * ATILE + r * AP))[q4] = kl[q4];
            const uint4* vh = (const uint4*)(g_Vth + (v_row0 + r) * Sn + kt * 64);
            const uint4* vl = (const uint4*)(g_Vtl + (v_row0 + r) * Sn + kt * 64);
            ((uint4*)(smu + 4 * ATILE + r * AP))[q4] = vh[q4];
            ((uint4*)(smu + 5 * ATILE + r * AP))[q4] = vl[q4];
        }
        __syncthreads();

        float s[8][4];
        #pragma unroll
        for (int ni = 0; ni < 8; ni++)
            #pragma unroll
            for (int c = 0; c < 4; c++) s[ni][c] = 0.0f;

        #pragma unroll
        for (int kk = 0; kk < 4; kk++) {
            unsigned ah[4], al[4];
            ldsm4(ah[0], ah[1], ah[2], ah[3], smu_b + q_loff + kk * 32);
            ldsm4(al[0], al[1], al[2], al[3], smu_b + ATB + q_loff + kk * 32);
            #pragma unroll
            for (int p = 0; p < 4; p++) {
                unsigned bh[4], bl[4];
                unsigned kd = smu_b + 2 * ATB + n_loff + (unsigned)(p * 16 * 144 + kk * 32);
                ldsm4(bh[0], bh[1], bh[2], bh[3], kd);
                ldsm4(bl[0], bl[1], bl[2], bl[3], kd + ATB);
                mma16816(s[2*p],   ah, bh);
                mma16816(s[2*p],   ah, bl);
                mma16816(s[2*p],   al, bh);
                mma16816(s[2*p+1], ah, bh + 2);
                mma16816(s[2*p+1], ah, bl + 2);
                mma16816(s[2*p+1], al, bh + 2);
            }
        }

        if (kt == qt) {
            #pragma unroll
            for (int ni = 0; ni < 8; ni++) {
                int col = ni * 8 + 2 * tig;
                int r0 = m0r + g, r1 = r0 + 8;
                if (col > r0)     s[ni][0] = -INFINITY;
                if (col + 1 > r0) s[ni][1] = -INFINITY;
                if (col > r1)     s[ni][2] = -INFINITY;
                if (col + 1 > r1) s[ni][3] = -INFINITY;
            }
        }

        float rm0 = -INFINITY, rm1 = -INFINITY;
        #pragma unroll
        for (int ni = 0; ni < 8; ni++) {
            rm0 = fmaxf(rm0, fmaxf(s[ni][0], s[ni][1]));
            rm1 = fmaxf(rm1, fmaxf(s[ni][2], s[ni][3]));
        }
        rm0 = fmaxf(rm0, __shfl_xor_sync(0xffffffffu, rm0, 1));
        rm0 = fmaxf(rm0, __shfl_xor_sync(0xffffffffu, rm0, 2));
        rm1 = fmaxf(rm1, __shfl_xor_sync(0xffffffffu, rm1, 1));
        rm1 = fmaxf(rm1, __shfl_xor_sync(0xffffffffu, rm1, 2));
        float mn0 = fmaxf(m0, rm0), mn1 = fmaxf(m1, rm1);

        float rs0 = 0.0f, rs1 = 0.0f;
        #pragma unroll
        for (int ni = 0; ni < 8; ni++) {
            s[ni][0] = __expf(s[ni][0] - mn0);
            s[ni][1] = __expf(s[ni][1] - mn0);
            s[ni][2] = __expf(s[ni][2] - mn1);
            s[ni][3] = __expf(s[ni][3] - mn1);
            rs0 += s[ni][0] + s[ni][1];
            rs1 += s[ni][2] + s[ni][3];
        }
        rs0 += __shfl_xor_sync(0xffffffffu, rs0, 1);
        rs0 += __shfl_xor_sync(0xffffffffu, rs0, 2);
        rs1 += __shfl_xor_sync(0xffffffffu, rs1, 1);
        rs1 += __shfl_xor_sync(0xffffffffu, rs1, 2);

        float al0 = __expf(m0 - mn0), al1 = __expf(m1 - mn1);
        l0 = l0 * al0 + rs0;
        l1 = l1 * al1 + rs1;
        m0 = mn0; m1 = mn1;
        #pragma unroll
        for (int ni = 0; ni < 8; ni++) {
            o[ni][0] *= al0; o[ni][1] *= al0;
            o[ni][2] *= al1; o[ni][3] *= al1;
        }

        #pragma unroll
        for (int kk = 0; kk < 4; kk++) {
            unsigned pah[4], pal[4];
            {
                __nv_bfloat16 h00,l00,h01,l01,h10,l10,h11,l11;
                split_bf16(s[2*kk][0], h00, l00);
                split_bf16(s[2*kk][1], h01, l01);
                split_bf16(s[2*kk][2], h10, l10);
                split_bf16(s[2*kk][3], h11, l11);
                pah[0] = pack2(h00, h01); pal[0] = pack2(l00, l01);
                pah[1] = pack2(h10, h11); pal[1] = pack2(l10, l11);
                split_bf16(s[2*kk+1][0], h00, l00);
                split_bf16(s[2*kk+1][1], h01, l01);
                split_bf16(s[2*kk+1][2], h10, l10);
                split_bf16(s[2*kk+1][3], h11, l11);
                pah[2] = pack2(h00, h01); pal[2] = pack2(l00, l01);
                pah[3] = pack2(h10, h11); pal[3] = pack2(l10, l11);
            }
            #pragma unroll
            for (int p = 0; p < 4; p++) {
                unsigned vh[4], vl[4];
                unsigned vd = smu_b + 4 * ATB + n_loff + (unsigned)(p * 16 * 144 + kk * 32);
                ldsm4(vh[0], vh[1], vh[2], vh[3], vd);
                ldsm4(vl[0], vl[1], vl[2], vl[3], vd + ATB);
                mma16816(o[2*p],   pah, vh);
                mma16816(o[2*p],   pah, vl);
                mma16816(o[2*p],   pal, vh);
                mma16816(o[2*p+1], pah, vh + 2);
                mma16816(o[2*p+1], pah, vl + 2);
                mma16816(o[2*p+1], pal, vh + 2);
            }
        }
        __syncthreads();
    }

    // finalize: z = O / l -> fp16 into g_Ah (O-proj A operand)
    float inv0 = 1.0f / l0, inv1 = 1.0f / l1;
    size_t row0 = rowQ0 + w * 16 + g;
    size_t row1 = row0 + 8;
    #pragma unroll
    for (int ni = 0; ni < 8; ni++) {
        int col = h * DH + ni * 8 + 2 * tig;
        __half2 z0(__float2half_rn(o[ni][0] * inv0), __float2half_rn(o[ni][1] * inv0));
        __half2 z1(__float2half_rn(o[ni][2] * inv1), __float2half_rn(o[ni][3] * inv1));
        *(__half2*)&g_Ah[row0 * Dn + col] = z0;
        *(__half2*)&g_Ah[row1 * Dn + col] = z1;
    }
}

// ---------------------------------------------------------------------------
extern "C" void kernel_launch(void* const* d_in, const int* in_sizes, int n_in,
                              void* d_out, int out_size) {
    const float* x     = (const float*)d_in[0];
    const float* W_qkv = (const float*)d_in[2];
    const float* b_qkv = (const float*)d_in[3];
    const float* W_o   = (const float*)d_in[4];
    const float* b_o   = (const float*)d_in[5];
    const float* wq    = (const float*)d_in[6];
    const float* wk    = (const float*)d_in[7];
    float* out = (float*)d_out;

    void *qkv_ptr, *ah, *wth, *wtl, *woth, *wotl;
    cudaGetSymbolAddress(&qkv_ptr, g_qkv);
    cudaGetSymbolAddress(&ah, g_Ah);
    cudaGetSymbolAddress(&wth, g_Wth);
    cudaGetSymbolAddress(&wtl, g_Wtl);
    cudaGetSymbolAddress(&woth, g_Woth);
    cudaGetSymbolAddress(&wotl, g_Wotl);

    cudaFuncSetAttribute(gemm_f16x2,
                         cudaFuncAttributeMaxDynamicSharedMemorySize, GEMM_SMEM);
    const int attn_smem = 6 * ATILE * 4;       // 55296 B
    cudaFuncSetAttribute(attn_mma_kernel,
                         cudaFuncAttributeMaxDynamicSharedMemorySize, attn_smem);

    // 0) Preprocessing: x -> fp16; transpose+split weights (fp16 hi/lo)
    cvt_f16_kernel<<<1024, 256>>>(x, (__half*)ah, (size_t)Mrows * Dn / 4);
    {
        dim3 grid(N3 / 32, Dn / 32);
        tsplit_f16_kernel<<<grid, dim3(32, 8)>>>(W_qkv, (__half*)wth,
                                                 (__half*)wtl, Dn, N3);
    }
    {
        dim3 grid(Dn / 32, Dn / 32);
        tsplit_f16_kernel<<<grid, dim3(32, 8)>>>(W_o, (__half*)woth,
                                                 (__half*)wotl, Dn, Dn);
    }

    // 1) QKV GEMM (fp16x2)
    {
        dim3 grid(N3 / 128, Mrows / 128);
        gemm_f16x2<<<grid, 256, GEMM_SMEM>>>(
            (const __half*)ah, (const __half*)wth, (const __half*)wtl,
            b_qkv, (float*)qkv_ptr, N3, Dn);
    }

    // 2) RMSNorm + split q,k (bf16); transpose-split v (bf16)
    {
        int total_warps = Mrows * NH * 2;
        int blocks = (total_warps * 32) / 256;
        rmsnorm_split_kernel<<<blocks, 256>>>(wq, wk);
    }
    {
        dim3 grid(Sn / 64, NH, Bn);
        vsplit_kernel<<<grid, 256>>>();
    }

    // 3) Flash attention (bf16x3 mma.sync) — writes fp16 z into g_Ah
    {
        dim3 grid(Sn / 64, NH, Bn);
        attn_mma_kernel<<<grid, 128, attn_smem>>>();
    }

    // 4) Output projection (fp16x2)
    {
        dim3 grid(Dn / 128, Mrows / 128);
        gemm_f16x2<<<grid, 256, GEMM_SMEM>>>(
            (const __half*)ah, (const __half*)woth, (const __half*)wotl,
            b_o, out, Dn, Dn);
    }
}